// round 3
// baseline (speedup 1.0000x reference)
#include <cuda_runtime.h>
#include <cuda_bf16.h>
#include <mma.h>
#include <math.h>

using namespace nvcuda;

#define BATCH   2
#define SEQ     2048
#define DMODEL  1024
#define NH      16
#define DH      64

// ---------------- scratch (allocation-free: __device__ globals) ----------------
__device__ float g_Qp[BATCH * SEQ * DMODEL];
__device__ float g_Kp[BATCH * SEQ * DMODEL];
__device__ float g_Vp[BATCH * SEQ * DMODEL];
__device__ float g_Ctx[BATCH * SEQ * DMODEL];

// ---------------- tf32 WMMA GEMM: C[M,1024] = A[M,1024] * B[1024,1024] ----------
// block tile 128x64, K-step 32, 256 threads (8 warps: 4 in M x 2 in N, 32x32 each)
__global__ __launch_bounds__(256) void gemm_tf32(const float* __restrict__ A,
                                                 const float* __restrict__ B,
                                                 float* __restrict__ C) {
    const int K = 1024, N = 1024;
    __shared__ float Ash[128][36];
    __shared__ float Bsh[32][68];

    const int t   = threadIdx.x;
    const int wid = t >> 5;
    const int wm  = wid & 3;   // 0..3
    const int wn  = wid >> 2;  // 0..1
    const int m0  = blockIdx.y * 128;
    const int n0  = blockIdx.x * 64;

    wmma::fragment<wmma::accumulator, 16, 16, 8, float> acc[2][2];
#pragma unroll
    for (int i = 0; i < 2; i++)
#pragma unroll
        for (int j = 0; j < 2; j++)
            wmma::fill_fragment(acc[i][j], 0.0f);

    for (int k0 = 0; k0 < K; k0 += 32) {
        __syncthreads();
        // load A tile 128x32
#pragma unroll
        for (int p = 0; p < 4; p++) {
            int row = p * 32 + (t >> 3);
            int col = (t & 7) * 4;
            *(float4*)&Ash[row][col] =
                *(const float4*)&A[(size_t)(m0 + row) * K + k0 + col];
        }
        // load B tile 32x64
#pragma unroll
        for (int p = 0; p < 2; p++) {
            int row = p * 16 + (t >> 4);
            int col = (t & 15) * 4;
            *(float4*)&Bsh[row][col] =
                *(const float4*)&B[(size_t)(k0 + row) * N + n0 + col];
        }
        __syncthreads();

#pragma unroll
        for (int kk = 0; kk < 4; kk++) {
            wmma::fragment<wmma::matrix_a, 16, 16, 8, wmma::precision::tf32, wmma::row_major> af[2];
            wmma::fragment<wmma::matrix_b, 16, 16, 8, wmma::precision::tf32, wmma::row_major> bf[2];
#pragma unroll
            for (int i = 0; i < 2; i++) {
                wmma::load_matrix_sync(af[i], &Ash[wm * 32 + 16 * i][kk * 8], 36);
#pragma unroll
                for (int e = 0; e < af[i].num_elements; e++)
                    af[i].x[e] = wmma::__float_to_tf32(af[i].x[e]);
            }
#pragma unroll
            for (int j = 0; j < 2; j++) {
                wmma::load_matrix_sync(bf[j], &Bsh[kk * 8][wn * 32 + 16 * j], 68);
#pragma unroll
                for (int e = 0; e < bf[j].num_elements; e++)
                    bf[j].x[e] = wmma::__float_to_tf32(bf[j].x[e]);
            }
#pragma unroll
            for (int i = 0; i < 2; i++)
#pragma unroll
                for (int j = 0; j < 2; j++)
                    wmma::mma_sync(acc[i][j], af[i], bf[j], acc[i][j]);
        }
    }

#pragma unroll
    for (int i = 0; i < 2; i++)
#pragma unroll
        for (int j = 0; j < 2; j++)
            wmma::store_matrix_sync(
                &C[(size_t)(m0 + wm * 32 + 16 * i) * N + n0 + wn * 32 + 16 * j],
                acc[i][j], N, wmma::mem_row_major);
}

// ---------------- causal flash attention (tf32 wmma), per (b, h, 64-q-tile) ----
#define BQ  64
#define BK  64
#define LDS 68

struct AttnSmem {
    float Q[BQ][LDS];
    float K[BK][LDS];
    float V[BK][LDS];
    float S[BQ][LDS];
    float m[BQ];
    float l[BQ];
    float alpha[BQ];
};

extern __shared__ unsigned char attn_smem_raw[];

__global__ __launch_bounds__(128) void attn_kernel() {
    AttnSmem& sm = *reinterpret_cast<AttnSmem*>(attn_smem_raw);

    const int t    = threadIdx.x;
    const int lane = t & 31;
    const int w    = t >> 5;           // warp 0..3 -> 16 rows each
    const int q0   = blockIdx.x * BQ;
    const int h    = blockIdx.y;
    const int b    = blockIdx.z;

    const float* Qp = g_Qp + (size_t)b * SEQ * DMODEL + h * DH;
    const float* Kp = g_Kp + (size_t)b * SEQ * DMODEL + h * DH;
    const float* Vp = g_Vp + (size_t)b * SEQ * DMODEL + h * DH;
    float*       Cp = g_Ctx + (size_t)b * SEQ * DMODEL + h * DH;

    // load Q tile (64x64)
#pragma unroll
    for (int p = 0; p < 8; p++) {
        int row = p * 8 + (t >> 4);
        int col = (t & 15) * 4;
        *(float4*)&sm.Q[row][col] =
            *(const float4*)&Qp[(size_t)(q0 + row) * DMODEL + col];
    }
    if (t < BQ) { sm.m[t] = -INFINITY; sm.l[t] = 0.0f; }

    // O accumulator: thread t owns row t/2, cols (t&1)*32 .. +32
    float O[32];
#pragma unroll
    for (int i = 0; i < 32; i++) O[i] = 0.0f;
    const int orow  = t >> 1;
    const int ocol0 = (t & 1) * 32;

    const int qtile = q0 / BK;
    const int nkt   = qtile + 1;

    for (int kt = 0; kt < nkt; kt++) {
        const int k0 = kt * BK;
        __syncthreads();
        // load K, V tiles (64x64 each)
#pragma unroll
        for (int p = 0; p < 8; p++) {
            int row = p * 8 + (t >> 4);
            int col = (t & 15) * 4;
            *(float4*)&sm.K[row][col] =
                *(const float4*)&Kp[(size_t)(k0 + row) * DMODEL + col];
            *(float4*)&sm.V[row][col] =
                *(const float4*)&Vp[(size_t)(k0 + row) * DMODEL + col];
        }
        __syncthreads();

        // --- S = Q * K^T  (per warp: rows w*16..+15, 4 col fragments) ---
        wmma::fragment<wmma::accumulator, 16, 16, 8, float> sacc[4];
#pragma unroll
        for (int j = 0; j < 4; j++) wmma::fill_fragment(sacc[j], 0.0f);
#pragma unroll
        for (int kk = 0; kk < 8; kk++) {
            wmma::fragment<wmma::matrix_a, 16, 16, 8, wmma::precision::tf32, wmma::row_major> af;
            wmma::load_matrix_sync(af, &sm.Q[w * 16][kk * 8], LDS);
#pragma unroll
            for (int e = 0; e < af.num_elements; e++)
                af.x[e] = wmma::__float_to_tf32(af.x[e]);
#pragma unroll
            for (int j = 0; j < 4; j++) {
                wmma::fragment<wmma::matrix_b, 16, 16, 8, wmma::precision::tf32, wmma::col_major> bf;
                wmma::load_matrix_sync(bf, &sm.K[j * 16][kk * 8], LDS);
#pragma unroll
                for (int e = 0; e < bf.num_elements; e++)
                    bf.x[e] = wmma::__float_to_tf32(bf.x[e]);
                wmma::mma_sync(sacc[j], af, bf, sacc[j]);
            }
        }
#pragma unroll
        for (int j = 0; j < 4; j++)
            wmma::store_matrix_sync(&sm.S[w * 16][j * 16], sacc[j], LDS, wmma::mem_row_major);
        __syncthreads();

        // --- online softmax on S (each warp does its 16 rows) ---
        const bool diag = (kt == qtile);
#pragma unroll 4
        for (int r = 0; r < 16; r++) {
            const int row = w * 16 + r;
            float s0 = sm.S[row][lane] * 0.125f;        // 1/sqrt(64)
            float s1 = sm.S[row][lane + 32] * 0.125f;
            bool msk0 = diag && (k0 + lane > q0 + row);
            bool msk1 = diag && (k0 + lane + 32 > q0 + row);
            if (msk0) s0 = -INFINITY;
            if (msk1) s1 = -INFINITY;
            float mx = fmaxf(s0, s1);
#pragma unroll
            for (int off = 16; off > 0; off >>= 1)
                mx = fmaxf(mx, __shfl_xor_sync(0xffffffffu, mx, off));
            const float mo = sm.m[row];
            const float mn = fmaxf(mo, mx);
            float p0 = msk0 ? 0.0f : __expf(s0 - mn);
            float p1 = msk1 ? 0.0f : __expf(s1 - mn);
            float sum = p0 + p1;
#pragma unroll
            for (int off = 16; off > 0; off >>= 1)
                sum += __shfl_xor_sync(0xffffffffu, sum, off);
            if (lane == 0) {
                float a = __expf(mo - mn);   // exp(-inf)=0 on first tile
                sm.alpha[row] = a;
                sm.l[row] = sm.l[row] * a + sum;
                sm.m[row] = mn;
            }
            sm.S[row][lane]      = p0;
            sm.S[row][lane + 32] = p1;
        }
        __syncthreads();

        // --- PV = P * V ---
        wmma::fragment<wmma::accumulator, 16, 16, 8, float> pacc[4];
#pragma unroll
        for (int j = 0; j < 4; j++) wmma::fill_fragment(pacc[j], 0.0f);
#pragma unroll
        for (int kk = 0; kk < 8; kk++) {
            wmma::fragment<wmma::matrix_a, 16, 16, 8, wmma::precision::tf32, wmma::row_major> af;
            wmma::load_matrix_sync(af, &sm.S[w * 16][kk * 8], LDS);
#pragma unroll
            for (int e = 0; e < af.num_elements; e++)
                af.x[e] = wmma::__float_to_tf32(af.x[e]);
#pragma unroll
            for (int j = 0; j < 4; j++) {
                wmma::fragment<wmma::matrix_b, 16, 16, 8, wmma::precision::tf32, wmma::row_major> bf;
                wmma::load_matrix_sync(bf, &sm.V[kk * 8][j * 16], LDS);
#pragma unroll
                for (int e = 0; e < bf.num_elements; e++)
                    bf.x[e] = wmma::__float_to_tf32(bf.x[e]);
                wmma::mma_sync(pacc[j], af, bf, pacc[j]);
            }
        }
        __syncthreads();   // everyone done reading S
#pragma unroll
        for (int j = 0; j < 4; j++)
            wmma::store_matrix_sync(&sm.S[w * 16][j * 16], pacc[j], LDS, wmma::mem_row_major);
        __syncthreads();

        // --- O = O*alpha + PV (register accumulator, known mapping) ---
        const float a = sm.alpha[orow];
#pragma unroll
        for (int i = 0; i < 32; i++)
            O[i] = O[i] * a + sm.S[orow][ocol0 + i];
    }

    // epilogue: divide by l, write context
    const float inv = 1.0f / sm.l[orow];
#pragma unroll
    for (int i = 0; i < 32; i += 4) {
        float4 v;
        v.x = O[i + 0] * inv;
        v.y = O[i + 1] * inv;
        v.z = O[i + 2] * inv;
        v.w = O[i + 3] * inv;
        *(float4*)&Cp[(size_t)(q0 + orow) * DMODEL + ocol0 + i] = v;
    }
}

// ---------------- launcher ----------------
extern "C" void kernel_launch(void* const* d_in, const int* in_sizes, int n_in,
                              void* d_out, int out_size) {
    const float* input_Q = (const float*)d_in[0];
    const float* input_K = (const float*)d_in[1];
    const float* input_V = (const float*)d_in[2];
    // d_in[3] = attn_mask (causal, implemented analytically), d_in[4] = flag
    const float* W_Q = (const float*)d_in[5];
    const float* W_K = (const float*)d_in[6];
    const float* W_V = (const float*)d_in[7];
    const float* W_O = (const float*)d_in[8];
    float* out = (float*)d_out;

    float *qp, *kp, *vp, *cp;
    cudaGetSymbolAddress((void**)&qp, g_Qp);
    cudaGetSymbolAddress((void**)&kp, g_Kp);
    cudaGetSymbolAddress((void**)&vp, g_Vp);
    cudaGetSymbolAddress((void**)&cp, g_Ctx);

    // opt-in to 70KB dynamic smem for attention (idempotent, capture-safe)
    cudaFuncSetAttribute(attn_kernel, cudaFuncAttributeMaxDynamicSharedMemorySize,
                         (int)sizeof(AttnSmem));

    const int M = BATCH * SEQ;               // 4096
    dim3 ggrid(DMODEL / 64, M / 128);        // (16, 32)
    dim3 gblk(256);

    gemm_tf32<<<ggrid, gblk>>>(input_Q, W_Q, qp);
    gemm_tf32<<<ggrid, gblk>>>(input_K, W_K, kp);
    gemm_tf32<<<ggrid, gblk>>>(input_V, W_V, vp);

    dim3 agrid(SEQ / BQ, NH, BATCH);         // (32, 16, 2)
    attn_kernel<<<agrid, 128, sizeof(AttnSmem)>>>();

    gemm_tf32<<<ggrid, gblk>>>(cp, W_O, out);
}

// round 7
// speedup vs baseline: 1.1629x; 1.1629x over previous
#include <cuda_runtime.h>
#include <cuda_bf16.h>
#include <mma.h>
#include <math.h>

using namespace nvcuda;

#define BATCH   2
#define SEQ     2048
#define DMODEL  1024
#define NH      16
#define DH      64

// ---------------- scratch (allocation-free: __device__ globals) ----------------
__device__ float g_Qp[BATCH * SEQ * DMODEL];
__device__ float g_Kp[BATCH * SEQ * DMODEL];
__device__ float g_Vp[BATCH * SEQ * DMODEL];
__device__ float g_Ctx[BATCH * SEQ * DMODEL];

__device__ __forceinline__ float to_tf32(float x) { return wmma::__float_to_tf32(x); }

// ================= tf32 WMMA GEMM: C[4096,1024] = A * B ======================
// 128x128 block tile, 256 threads, 8 warps (4 in M x 2 in N), each warp 32x64.
// K-step 16, double-buffered smem + register-prefetched global loads.
// blockIdx.z selects which (A,B,C) trio (fused QKV projections).
__global__ __launch_bounds__(256) void gemm_tf32(
    const float* __restrict__ A0, const float* __restrict__ A1, const float* __restrict__ A2,
    const float* __restrict__ B0, const float* __restrict__ B1, const float* __restrict__ B2,
    float* __restrict__ C0, float* __restrict__ C1, float* __restrict__ C2) {
    const int K = 1024, N = 1024;
    __shared__ float Ash[2][128][20];
    __shared__ float Bsh[2][16][132];

    const int z = blockIdx.z;
    const float* A = (z == 0) ? A0 : (z == 1) ? A1 : A2;
    const float* B = (z == 0) ? B0 : (z == 1) ? B1 : B2;
    float*       C = (z == 0) ? C0 : (z == 1) ? C1 : C2;

    const int t  = threadIdx.x;
    const int wid = t >> 5;
    const int wm  = wid & 3;    // 0..3 (M)
    const int wn  = wid >> 2;   // 0..1 (N)
    const int m0  = blockIdx.y * 128;
    const int n0  = blockIdx.x * 128;

    const int arow = t >> 2;         // + p*64
    const int ac   = (t & 3) * 4;
    const int brow = t >> 5;         // + p*8
    const int bc   = (t & 31) * 4;

    wmma::fragment<wmma::accumulator, 16, 16, 8, float> acc[2][4];
#pragma unroll
    for (int i = 0; i < 2; i++)
#pragma unroll
        for (int j = 0; j < 4; j++) wmma::fill_fragment(acc[i][j], 0.0f);

    float4 ra[2], rb[2];
    // prologue: load k-slice 0, store to buf 0
#pragma unroll
    for (int p = 0; p < 2; p++) {
        ra[p] = *(const float4*)&A[(size_t)(m0 + arow + p * 64) * K + ac];
        rb[p] = *(const float4*)&B[(size_t)(brow + p * 8) * N + n0 + bc];
    }
#pragma unroll
    for (int p = 0; p < 2; p++) {
        float* d = &Ash[0][arow + p * 64][ac];
        d[0] = to_tf32(ra[p].x); d[1] = to_tf32(ra[p].y);
        d[2] = to_tf32(ra[p].z); d[3] = to_tf32(ra[p].w);
        d = &Bsh[0][brow + p * 8][bc];
        d[0] = to_tf32(rb[p].x); d[1] = to_tf32(rb[p].y);
        d[2] = to_tf32(rb[p].z); d[3] = to_tf32(rb[p].w);
    }
    __syncthreads();

    int buf = 0;
    for (int kt = 0; kt < 64; kt++) {
        const int kn = (kt + 1) * 16;
        if (kt < 63) {
#pragma unroll
            for (int p = 0; p < 2; p++) {
                ra[p] = *(const float4*)&A[(size_t)(m0 + arow + p * 64) * K + kn + ac];
                rb[p] = *(const float4*)&B[(size_t)(kn + brow + p * 8) * N + n0 + bc];
            }
        }
#pragma unroll
        for (int kk = 0; kk < 2; kk++) {
            wmma::fragment<wmma::matrix_a, 16, 16, 8, wmma::precision::tf32, wmma::row_major> af[2];
            wmma::fragment<wmma::matrix_b, 16, 16, 8, wmma::precision::tf32, wmma::row_major> bf[4];
#pragma unroll
            for (int i = 0; i < 2; i++)
                wmma::load_matrix_sync(af[i], &Ash[buf][wm * 32 + 16 * i][kk * 8], 20);
#pragma unroll
            for (int j = 0; j < 4; j++)
                wmma::load_matrix_sync(bf[j], &Bsh[buf][kk * 8][wn * 64 + 16 * j], 132);
#pragma unroll
            for (int i = 0; i < 2; i++)
#pragma unroll
                for (int j = 0; j < 4; j++)
                    wmma::mma_sync(acc[i][j], af[i], bf[j], acc[i][j]);
        }
        if (kt < 63) {
            const int ob = buf ^ 1;
#pragma unroll
            for (int p = 0; p < 2; p++) {
                float* d = &Ash[ob][arow + p * 64][ac];
                d[0] = to_tf32(ra[p].x); d[1] = to_tf32(ra[p].y);
                d[2] = to_tf32(ra[p].z); d[3] = to_tf32(ra[p].w);
                d = &Bsh[ob][brow + p * 8][bc];
                d[0] = to_tf32(rb[p].x); d[1] = to_tf32(rb[p].y);
                d[2] = to_tf32(rb[p].z); d[3] = to_tf32(rb[p].w);
            }
        }
        __syncthreads();
        buf ^= 1;
    }

#pragma unroll
    for (int i = 0; i < 2; i++)
#pragma unroll
        for (int j = 0; j < 4; j++)
            wmma::store_matrix_sync(
                &C[(size_t)(m0 + wm * 32 + 16 * i) * N + n0 + wn * 64 + 16 * j],
                acc[i][j], N, wmma::mem_row_major);
}

// ================= causal flash attention (tf32 wmma) =========================
// 64x64 q/k tiles, 256 threads (8 warps: 4 row-groups x 2 col-groups).
// Softmax: 4 threads per row, 16 elems each, state (m,l) in registers.
#define BQ  64
#define BK  64
#define LDS 68

struct AttnSmem {
    float Q[BQ][LDS];
    float K[BK][LDS];
    float V[BK][LDS];
    float S[BQ][LDS];
};

extern __shared__ unsigned char attn_smem_raw[];

__global__ __launch_bounds__(256) void attn_kernel() {
    AttnSmem& sm = *reinterpret_cast<AttnSmem*>(attn_smem_raw);

    const int t  = threadIdx.x;
    const int w  = t >> 5;
    const int wm = w & 3;    // row group: rows wm*16..+15
    const int wn = w >> 2;   // col group: cols wn*32..+31
    const int qt = (int)gridDim.x - 1 - (int)blockIdx.x;  // heavy tiles first
    const int q0 = qt * BQ;
    const int h  = blockIdx.y;
    const int b  = blockIdx.z;

    const float* Qp = g_Qp + (size_t)b * SEQ * DMODEL + h * DH;
    const float* Kp = g_Kp + (size_t)b * SEQ * DMODEL + h * DH;
    const float* Vp = g_Vp + (size_t)b * SEQ * DMODEL + h * DH;
    float*       Cp = g_Ctx + (size_t)b * SEQ * DMODEL + h * DH;

    // load Q tile (scale by 1/sqrt(64) and convert to tf32 once)
#pragma unroll
    for (int p = 0; p < 4; p++) {
        int i = t + p * 256;
        int row = i >> 4, c = (i & 15) * 4;
        float4 v = *(const float4*)&Qp[(size_t)(q0 + row) * DMODEL + c];
        float* d = &sm.Q[row][c];
        d[0] = to_tf32(v.x * 0.125f); d[1] = to_tf32(v.y * 0.125f);
        d[2] = to_tf32(v.z * 0.125f); d[3] = to_tf32(v.w * 0.125f);
    }

    const int orow = t >> 2;         // 0..63
    const int oc0  = (t & 3) * 16;   // 0,16,32,48
    float O[16];
#pragma unroll
    for (int i = 0; i < 16; i++) O[i] = 0.0f;
    float m_r = -INFINITY, l_r = 0.0f;

    const int nkt = qt + 1;
    for (int kt = 0; kt < nkt; kt++) {
        const int k0 = kt * BK;
        // --- load K, V tiles (convert to tf32) ---
#pragma unroll
        for (int p = 0; p < 4; p++) {
            int i = t + p * 256;
            int row = i >> 4, c = (i & 15) * 4;
            float4 vk = *(const float4*)&Kp[(size_t)(k0 + row) * DMODEL + c];
            float4 vv = *(const float4*)&Vp[(size_t)(k0 + row) * DMODEL + c];
            float* d = &sm.K[row][c];
            d[0] = to_tf32(vk.x); d[1] = to_tf32(vk.y);
            d[2] = to_tf32(vk.z); d[3] = to_tf32(vk.w);
            d = &sm.V[row][c];
            d[0] = to_tf32(vv.x); d[1] = to_tf32(vv.y);
            d[2] = to_tf32(vv.z); d[3] = to_tf32(vv.w);
        }
        __syncthreads();   // (A) K,V visible; prior O-update S reads done

        // --- S = Q * K^T : warp computes rows wm*16, cols wn*32..+31 ---
        {
            wmma::fragment<wmma::accumulator, 16, 16, 8, float> sacc[2];
#pragma unroll
            for (int j = 0; j < 2; j++) wmma::fill_fragment(sacc[j], 0.0f);
#pragma unroll
            for (int kk = 0; kk < 8; kk++) {
                wmma::fragment<wmma::matrix_a, 16, 16, 8, wmma::precision::tf32, wmma::row_major> af;
                wmma::load_matrix_sync(af, &sm.Q[wm * 16][kk * 8], LDS);
#pragma unroll
                for (int j = 0; j < 2; j++) {
                    wmma::fragment<wmma::matrix_b, 16, 16, 8, wmma::precision::tf32, wmma::col_major> bf;
                    wmma::load_matrix_sync(bf, &sm.K[wn * 32 + 16 * j][kk * 8], LDS);
                    wmma::mma_sync(sacc[j], af, bf, sacc[j]);
                }
            }
#pragma unroll
            for (int j = 0; j < 2; j++)
                wmma::store_matrix_sync(&sm.S[wm * 16][wn * 32 + 16 * j], sacc[j],
                                        LDS, wmma::mem_row_major);
        }
        __syncthreads();   // (B) S complete

        // --- online softmax: 4 threads per row, 16 elems each ---
        {
            const int limit = q0 + orow - k0 - oc0;  // mask i > limit
            float sv[16];
            float mx = -INFINITY;
#pragma unroll
            for (int i = 0; i < 16; i++) {
                float s = sm.S[orow][oc0 + i];
                s = (i <= limit) ? s : -INFINITY;
                sv[i] = s;
                mx = fmaxf(mx, s);
            }
            mx = fmaxf(mx, __shfl_xor_sync(0xffffffffu, mx, 1));
            mx = fmaxf(mx, __shfl_xor_sync(0xffffffffu, mx, 2));
            const float mn = fmaxf(m_r, mx);
            float sum = 0.0f;
#pragma unroll
            for (int i = 0; i < 16; i++) {
                float p = __expf(sv[i] - mn);
                sm.S[orow][oc0 + i] = to_tf32(p);
                sum += p;
            }
            sum += __shfl_xor_sync(0xffffffffu, sum, 1);
            sum += __shfl_xor_sync(0xffffffffu, sum, 2);
            const float a = __expf(m_r - mn);   // 0 on first tile
            l_r = l_r * a + sum;
            m_r = mn;
            // stash alpha in sv[0] slot? keep in register:
            sv[0] = a;  // (compiler keeps 'a' live below anyway)
            __syncthreads();   // (C) P complete

            // --- PV = P * V ---
            wmma::fragment<wmma::accumulator, 16, 16, 8, float> pacc[2];
#pragma unroll
            for (int j = 0; j < 2; j++) wmma::fill_fragment(pacc[j], 0.0f);
#pragma unroll
            for (int kk = 0; kk < 8; kk++) {
                wmma::fragment<wmma::matrix_a, 16, 16, 8, wmma::precision::tf32, wmma::row_major> af;
                wmma::load_matrix_sync(af, &sm.S[wm * 16][kk * 8], LDS);
#pragma unroll
                for (int j = 0; j < 2; j++) {
                    wmma::fragment<wmma::matrix_b, 16, 16, 8, wmma::precision::tf32, wmma::row_major> bf;
                    wmma::load_matrix_sync(bf, &sm.V[kk * 8][wn * 32 + 16 * j], LDS);
                    wmma::mma_sync(pacc[j], af, bf, pacc[j]);
                }
            }
            __syncthreads();   // (D) all P reads done
#pragma unroll
            for (int j = 0; j < 2; j++)
                wmma::store_matrix_sync(&sm.S[wm * 16][wn * 32 + 16 * j], pacc[j],
                                        LDS, wmma::mem_row_major);
            __syncthreads();   // (E) PV result visible

            // --- O = O*alpha + PV ---
#pragma unroll
            for (int i = 0; i < 16; i++)
                O[i] = O[i] * a + sm.S[orow][oc0 + i];
        }
    }

    // epilogue: normalize and write context
    const float inv = 1.0f / l_r;
#pragma unroll
    for (int i = 0; i < 16; i += 4) {
        float4 v;
        v.x = O[i + 0] * inv; v.y = O[i + 1] * inv;
        v.z = O[i + 2] * inv; v.w = O[i + 3] * inv;
        *(float4*)&Cp[(size_t)(q0 + orow) * DMODEL + oc0 + i] = v;
    }
}

// ---------------- launcher ----------------
extern "C" void kernel_launch(void* const* d_in, const int* in_sizes, int n_in,
                              void* d_out, int out_size) {
    const float* input_Q = (const float*)d_in[0];
    const float* input_K = (const float*)d_in[1];
    const float* input_V = (const float*)d_in[2];
    // d_in[3] = attn_mask (causal, analytic), d_in[4] = flag
    const float* W_Q = (const float*)d_in[5];
    const float* W_K = (const float*)d_in[6];
    const float* W_V = (const float*)d_in[7];
    const float* W_O = (const float*)d_in[8];
    float* out = (float*)d_out;

    float *qp, *kp, *vp, *cp;
    cudaGetSymbolAddress((void**)&qp, g_Qp);
    cudaGetSymbolAddress((void**)&kp, g_Kp);
    cudaGetSymbolAddress((void**)&vp, g_Vp);
    cudaGetSymbolAddress((void**)&cp, g_Ctx);

    cudaFuncSetAttribute(attn_kernel, cudaFuncAttributeMaxDynamicSharedMemorySize,
                         (int)sizeof(AttnSmem));

    // fused QKV projections: grid.z selects operand trio
    dim3 ggrid(DMODEL / 128, (BATCH * SEQ) / 128, 3);   // (8, 32, 3)
    gemm_tf32<<<ggrid, 256>>>(input_Q, input_K, input_V,
                              W_Q, W_K, W_V,
                              qp, kp, vp);

    dim3 agrid(SEQ / BQ, NH, BATCH);                    // (32, 16, 2)
    attn_kernel<<<agrid, 256, sizeof(AttnSmem)>>>();

    // output projection
    dim3 ogrid(DMODEL / 128, (BATCH * SEQ) / 128, 1);
    gemm_tf32<<<ogrid, 256>>>(cp, cp, cp, W_O, W_O, W_O, out, out, out);
}

// round 12
// speedup vs baseline: 1.1963x; 1.0287x over previous
#include <cuda_runtime.h>
#include <cuda_bf16.h>
#include <mma.h>
#include <math.h>

using namespace nvcuda;

#define BATCH   2
#define SEQ     2048
#define DMODEL  1024
#define NH      16
#define DH      64

// ---------------- scratch (allocation-free: __device__ globals) ----------------
__device__ float g_Qp[BATCH * SEQ * DMODEL];
__device__ float g_Kp[BATCH * SEQ * DMODEL];
__device__ float g_Vp[BATCH * SEQ * DMODEL];
__device__ float g_Ctx[BATCH * SEQ * DMODEL];

__device__ __forceinline__ float to_tf32(float x) { return wmma::__float_to_tf32(x); }

// ================= tf32 WMMA GEMM: C[4096,1024] = A * B ======================
// 128x128 block tile, 256 threads, 8 warps (4 in M x 2 in N), each warp 32x64.
// K-step 16, double-buffered smem + register-prefetched global loads.
// __launch_bounds__(256,2): cap 128 regs/thread -> 2 CTAs/SM (was 136 regs, 1 CTA).
// blockIdx.z selects which (A,B,C) trio (fused QKV projections).
__global__ __launch_bounds__(256, 2) void gemm_tf32(
    const float* __restrict__ A0, const float* __restrict__ A1, const float* __restrict__ A2,
    const float* __restrict__ B0, const float* __restrict__ B1, const float* __restrict__ B2,
    float* __restrict__ C0, float* __restrict__ C1, float* __restrict__ C2) {
    const int K = 1024, N = 1024;
    __shared__ float Ash[2][128][20];
    __shared__ float Bsh[2][16][132];

    const int z = blockIdx.z;
    const float* A = (z == 0) ? A0 : (z == 1) ? A1 : A2;
    const float* B = (z == 0) ? B0 : (z == 1) ? B1 : B2;
    float*       C = (z == 0) ? C0 : (z == 1) ? C1 : C2;

    const int t  = threadIdx.x;
    const int wid = t >> 5;
    const int wm  = wid & 3;    // 0..3 (M)
    const int wn  = wid >> 2;   // 0..1 (N)
    const int m0  = blockIdx.y * 128;
    const int n0  = blockIdx.x * 128;

    const int arow = t >> 2;         // + p*64
    const int ac   = (t & 3) * 4;
    const int brow = t >> 5;         // + p*8
    const int bc   = (t & 31) * 4;

    wmma::fragment<wmma::accumulator, 16, 16, 8, float> acc[2][4];
#pragma unroll
    for (int i = 0; i < 2; i++)
#pragma unroll
        for (int j = 0; j < 4; j++) wmma::fill_fragment(acc[i][j], 0.0f);

    float4 ra[2], rb[2];
    // prologue: load k-slice 0, store to buf 0
#pragma unroll
    for (int p = 0; p < 2; p++) {
        ra[p] = *(const float4*)&A[(size_t)(m0 + arow + p * 64) * K + ac];
        rb[p] = *(const float4*)&B[(size_t)(brow + p * 8) * N + n0 + bc];
    }
#pragma unroll
    for (int p = 0; p < 2; p++) {
        float* d = &Ash[0][arow + p * 64][ac];
        d[0] = to_tf32(ra[p].x); d[1] = to_tf32(ra[p].y);
        d[2] = to_tf32(ra[p].z); d[3] = to_tf32(ra[p].w);
        d = &Bsh[0][brow + p * 8][bc];
        d[0] = to_tf32(rb[p].x); d[1] = to_tf32(rb[p].y);
        d[2] = to_tf32(rb[p].z); d[3] = to_tf32(rb[p].w);
    }
    __syncthreads();

    int buf = 0;
    for (int kt = 0; kt < 64; kt++) {
        const int kn = (kt + 1) * 16;
        if (kt < 63) {
#pragma unroll
            for (int p = 0; p < 2; p++) {
                ra[p] = *(const float4*)&A[(size_t)(m0 + arow + p * 64) * K + kn + ac];
                rb[p] = *(const float4*)&B[(size_t)(kn + brow + p * 8) * N + n0 + bc];
            }
        }
#pragma unroll
        for (int kk = 0; kk < 2; kk++) {
            wmma::fragment<wmma::matrix_a, 16, 16, 8, wmma::precision::tf32, wmma::row_major> af[2];
            wmma::fragment<wmma::matrix_b, 16, 16, 8, wmma::precision::tf32, wmma::row_major> bf[4];
#pragma unroll
            for (int i = 0; i < 2; i++)
                wmma::load_matrix_sync(af[i], &Ash[buf][wm * 32 + 16 * i][kk * 8], 20);
#pragma unroll
            for (int j = 0; j < 4; j++)
                wmma::load_matrix_sync(bf[j], &Bsh[buf][kk * 8][wn * 64 + 16 * j], 132);
#pragma unroll
            for (int i = 0; i < 2; i++)
#pragma unroll
                for (int j = 0; j < 4; j++)
                    wmma::mma_sync(acc[i][j], af[i], bf[j], acc[i][j]);
        }
        if (kt < 63) {
            const int ob = buf ^ 1;
#pragma unroll
            for (int p = 0; p < 2; p++) {
                float* d = &Ash[ob][arow + p * 64][ac];
                d[0] = to_tf32(ra[p].x); d[1] = to_tf32(ra[p].y);
                d[2] = to_tf32(ra[p].z); d[3] = to_tf32(ra[p].w);
                d = &Bsh[ob][brow + p * 8][bc];
                d[0] = to_tf32(rb[p].x); d[1] = to_tf32(rb[p].y);
                d[2] = to_tf32(rb[p].z); d[3] = to_tf32(rb[p].w);
            }
        }
        __syncthreads();
        buf ^= 1;
    }

#pragma unroll
    for (int i = 0; i < 2; i++)
#pragma unroll
        for (int j = 0; j < 4; j++)
            wmma::store_matrix_sync(
                &C[(size_t)(m0 + wm * 32 + 16 * i) * N + n0 + wn * 64 + 16 * j],
                acc[i][j], N, wmma::mem_row_major);
}

// ================= causal flash attention (tf32 wmma) =========================
// BQ=128 q-rows per CTA, BK=64 k-tile, 256 threads (8 warps, one 16-row group each).
// Softmax: 2 threads per row, 32 elems each (single xor-1 shuffle), two-pass over
// smem to keep registers under the 128/thread cap (2 CTAs/SM at 104.4 KB smem).
#define BQ  128
#define BK  64
#define LDS 68

struct AttnSmem {
    float Q[BQ][LDS];
    float K[BK][LDS];
    float V[BK][LDS];
    float S[BQ][LDS];
};

extern __shared__ unsigned char attn_smem_raw[];

__global__ __launch_bounds__(256, 2) void attn_kernel() {
    AttnSmem& sm = *reinterpret_cast<AttnSmem*>(attn_smem_raw);

    const int t  = threadIdx.x;
    const int w  = t >> 5;                               // 0..7: rows w*16..+15
    const int qt = (int)gridDim.x - 1 - (int)blockIdx.x; // heavy tiles first
    const int q0 = qt * BQ;
    const int h  = blockIdx.y;
    const int b  = blockIdx.z;

    const float* Qp = g_Qp + (size_t)b * SEQ * DMODEL + h * DH;
    const float* Kp = g_Kp + (size_t)b * SEQ * DMODEL + h * DH;
    const float* Vp = g_Vp + (size_t)b * SEQ * DMODEL + h * DH;
    float*       Cp = g_Ctx + (size_t)b * SEQ * DMODEL + h * DH;

    // load Q tile 128x64 (scale by 1/sqrt(64), convert to tf32 once)
#pragma unroll
    for (int p = 0; p < 8; p++) {
        int i = t + p * 256;
        int row = i >> 4, c = (i & 15) * 4;
        float4 v = *(const float4*)&Qp[(size_t)(q0 + row) * DMODEL + c];
        float* d = &sm.Q[row][c];
        d[0] = to_tf32(v.x * 0.125f); d[1] = to_tf32(v.y * 0.125f);
        d[2] = to_tf32(v.z * 0.125f); d[3] = to_tf32(v.w * 0.125f);
    }

    const int orow = t >> 1;          // 0..127
    const int oc0  = (t & 1) * 32;    // 0 or 32
    float O[32];
#pragma unroll
    for (int i = 0; i < 32; i++) O[i] = 0.0f;
    float m_r = -INFINITY, l_r = 0.0f;

    const int nkt = 2 * qt + 2;       // k-tiles up to and including diagonal
    for (int kt = 0; kt < nkt; kt++) {
        const int k0 = kt * BK;
        // --- load K, V tiles 64x64 (convert to tf32) ---
#pragma unroll
        for (int p = 0; p < 4; p++) {
            int i = t + p * 256;
            int row = i >> 4, c = (i & 15) * 4;
            float4 vk = *(const float4*)&Kp[(size_t)(k0 + row) * DMODEL + c];
            float4 vv = *(const float4*)&Vp[(size_t)(k0 + row) * DMODEL + c];
            float* d = &sm.K[row][c];
            d[0] = to_tf32(vk.x); d[1] = to_tf32(vk.y);
            d[2] = to_tf32(vk.z); d[3] = to_tf32(vk.w);
            d = &sm.V[row][c];
            d[0] = to_tf32(vv.x); d[1] = to_tf32(vv.y);
            d[2] = to_tf32(vv.z); d[3] = to_tf32(vv.w);
        }
        __syncthreads();   // (A) K,V visible; prior-iter S reads (O update) done

        // --- S = Q * K^T : warp w computes rows w*16..+15, all 64 cols ---
        {
            wmma::fragment<wmma::accumulator, 16, 16, 8, float> sacc[4];
#pragma unroll
            for (int j = 0; j < 4; j++) wmma::fill_fragment(sacc[j], 0.0f);
#pragma unroll
            for (int kk = 0; kk < 8; kk++) {
                wmma::fragment<wmma::matrix_a, 16, 16, 8, wmma::precision::tf32, wmma::row_major> af;
                wmma::load_matrix_sync(af, &sm.Q[w * 16][kk * 8], LDS);
#pragma unroll
                for (int j = 0; j < 4; j++) {
                    wmma::fragment<wmma::matrix_b, 16, 16, 8, wmma::precision::tf32, wmma::col_major> bf;
                    wmma::load_matrix_sync(bf, &sm.K[j * 16][kk * 8], LDS);
                    wmma::mma_sync(sacc[j], af, bf, sacc[j]);
                }
            }
#pragma unroll
            for (int j = 0; j < 4; j++)
                wmma::store_matrix_sync(&sm.S[w * 16][j * 16], sacc[j], LDS,
                                        wmma::mem_row_major);
        }
        __syncthreads();   // (B) S complete

        // --- online softmax: 2 threads/row, 32 elems each, two-pass ---
        {
            const int limit = q0 + orow - k0 - oc0;   // mask i > limit
            float mx = -INFINITY;
#pragma unroll
            for (int i = 0; i < 32; i++) {
                float s = sm.S[orow][oc0 + i];
                mx = fmaxf(mx, (i <= limit) ? s : -INFINITY);
            }
            mx = fmaxf(mx, __shfl_xor_sync(0xffffffffu, mx, 1));
            const float mn = fmaxf(m_r, mx);
            float sum = 0.0f;
#pragma unroll
            for (int i = 0; i < 32; i++) {
                float s = sm.S[orow][oc0 + i];
                float p = (i <= limit) ? __expf(s - mn) : 0.0f;
                sm.S[orow][oc0 + i] = to_tf32(p);
                sum += p;
            }
            sum += __shfl_xor_sync(0xffffffffu, sum, 1);
            const float a = __expf(m_r - mn);   // 0 on first tile
            l_r = l_r * a + sum;
            m_r = mn;
            __syncthreads();   // (C) P complete

            // --- PV = P * V : warp w rows w*16..+15, all 64 cols ---
            wmma::fragment<wmma::accumulator, 16, 16, 8, float> pacc[4];
#pragma unroll
            for (int j = 0; j < 4; j++) wmma::fill_fragment(pacc[j], 0.0f);
#pragma unroll
            for (int kk = 0; kk < 8; kk++) {
                wmma::fragment<wmma::matrix_a, 16, 16, 8, wmma::precision::tf32, wmma::row_major> af;
                wmma::load_matrix_sync(af, &sm.S[w * 16][kk * 8], LDS);
#pragma unroll
                for (int j = 0; j < 4; j++) {
                    wmma::fragment<wmma::matrix_b, 16, 16, 8, wmma::precision::tf32, wmma::row_major> bf;
                    wmma::load_matrix_sync(bf, &sm.V[kk * 8][j * 16], LDS);
                    wmma::mma_sync(pacc[j], af, bf, pacc[j]);
                }
            }
            __syncthreads();   // (D) all P reads done
#pragma unroll
            for (int j = 0; j < 4; j++)
                wmma::store_matrix_sync(&sm.S[w * 16][j * 16], pacc[j], LDS,
                                        wmma::mem_row_major);
            __syncthreads();   // (E) PV result visible

            // --- O = O*alpha + PV ---
#pragma unroll
            for (int i = 0; i < 32; i++)
                O[i] = O[i] * a + sm.S[orow][oc0 + i];
        }
    }

    // epilogue: normalize and write context
    const float inv = 1.0f / l_r;
#pragma unroll
    for (int i = 0; i < 32; i += 4) {
        float4 v;
        v.x = O[i + 0] * inv; v.y = O[i + 1] * inv;
        v.z = O[i + 2] * inv; v.w = O[i + 3] * inv;
        *(float4*)&Cp[(size_t)(q0 + orow) * DMODEL + oc0 + i] = v;
    }
}

// ---------------- launcher ----------------
extern "C" void kernel_launch(void* const* d_in, const int* in_sizes, int n_in,
                              void* d_out, int out_size) {
    const float* input_Q = (const float*)d_in[0];
    const float* input_K = (const float*)d_in[1];
    const float* input_V = (const float*)d_in[2];
    // d_in[3] = attn_mask (causal, analytic), d_in[4] = flag
    const float* W_Q = (const float*)d_in[5];
    const float* W_K = (const float*)d_in[6];
    const float* W_V = (const float*)d_in[7];
    const float* W_O = (const float*)d_in[8];
    float* out = (float*)d_out;

    float *qp, *kp, *vp, *cp;
    cudaGetSymbolAddress((void**)&qp, g_Qp);
    cudaGetSymbolAddress((void**)&kp, g_Kp);
    cudaGetSymbolAddress((void**)&vp, g_Vp);
    cudaGetSymbolAddress((void**)&cp, g_Ctx);

    cudaFuncSetAttribute(attn_kernel, cudaFuncAttributeMaxDynamicSharedMemorySize,
                         (int)sizeof(AttnSmem));

    // fused QKV projections: grid.z selects operand trio
    dim3 ggrid(DMODEL / 128, (BATCH * SEQ) / 128, 3);   // (8, 32, 3)
    gemm_tf32<<<ggrid, 256>>>(input_Q, input_K, input_V,
                              W_Q, W_K, W_V,
                              qp, kp, vp);

    dim3 agrid(SEQ / BQ, NH, BATCH);                    // (16, 16, 2)
    attn_kernel<<<agrid, 256, sizeof(AttnSmem)>>>();

    // output projection
    dim3 ogrid(DMODEL / 128, (BATCH * SEQ) / 128, 1);
    gemm_tf32<<<ogrid, 256>>>(cp, cp, cp, W_O, W_O, W_O, out, out, out);
}

// round 13
// speedup vs baseline: 1.9831x; 1.6577x over previous
#include <cuda_runtime.h>
#include <cuda_bf16.h>
#include <cuda_fp16.h>
#include <mma.h>
#include <math.h>
#include <cstdint>
#include <cstring>

using namespace nvcuda;

#define BATCH   2
#define SEQ     2048
#define DMODEL  1024
#define NH      16
#define DH      64

// ---------------- scratch (allocation-free: __device__ globals) ----------------
__device__ float g_Qp[BATCH * SEQ * DMODEL];
__device__ float g_Kp[BATCH * SEQ * DMODEL];
__device__ float g_Vp[BATCH * SEQ * DMODEL];
__device__ float g_Ctx[BATCH * SEQ * DMODEL];

__device__ __forceinline__ float to_tf32(float x) { return wmma::__float_to_tf32(x); }

// ================= tf32 WMMA GEMM (unchanged from R12, passing) ===============
__global__ __launch_bounds__(256, 2) void gemm_tf32(
    const float* __restrict__ A0, const float* __restrict__ A1, const float* __restrict__ A2,
    const float* __restrict__ B0, const float* __restrict__ B1, const float* __restrict__ B2,
    float* __restrict__ C0, float* __restrict__ C1, float* __restrict__ C2) {
    const int K = 1024, N = 1024;
    __shared__ float Ash[2][128][20];
    __shared__ float Bsh[2][16][132];

    const int z = blockIdx.z;
    const float* A = (z == 0) ? A0 : (z == 1) ? A1 : A2;
    const float* B = (z == 0) ? B0 : (z == 1) ? B1 : B2;
    float*       C = (z == 0) ? C0 : (z == 1) ? C1 : C2;

    const int t  = threadIdx.x;
    const int wid = t >> 5;
    const int wm  = wid & 3;
    const int wn  = wid >> 2;
    const int m0  = blockIdx.y * 128;
    const int n0  = blockIdx.x * 128;

    const int arow = t >> 2;
    const int ac   = (t & 3) * 4;
    const int brow = t >> 5;
    const int bc   = (t & 31) * 4;

    wmma::fragment<wmma::accumulator, 16, 16, 8, float> acc[2][4];
#pragma unroll
    for (int i = 0; i < 2; i++)
#pragma unroll
        for (int j = 0; j < 4; j++) wmma::fill_fragment(acc[i][j], 0.0f);

    float4 ra[2], rb[2];
#pragma unroll
    for (int p = 0; p < 2; p++) {
        ra[p] = *(const float4*)&A[(size_t)(m0 + arow + p * 64) * K + ac];
        rb[p] = *(const float4*)&B[(size_t)(brow + p * 8) * N + n0 + bc];
    }
#pragma unroll
    for (int p = 0; p < 2; p++) {
        float* d = &Ash[0][arow + p * 64][ac];
        d[0] = to_tf32(ra[p].x); d[1] = to_tf32(ra[p].y);
        d[2] = to_tf32(ra[p].z); d[3] = to_tf32(ra[p].w);
        d = &Bsh[0][brow + p * 8][bc];
        d[0] = to_tf32(rb[p].x); d[1] = to_tf32(rb[p].y);
        d[2] = to_tf32(rb[p].z); d[3] = to_tf32(rb[p].w);
    }
    __syncthreads();

    int buf = 0;
    for (int kt = 0; kt < 64; kt++) {
        const int kn = (kt + 1) * 16;
        if (kt < 63) {
#pragma unroll
            for (int p = 0; p < 2; p++) {
                ra[p] = *(const float4*)&A[(size_t)(m0 + arow + p * 64) * K + kn + ac];
                rb[p] = *(const float4*)&B[(size_t)(kn + brow + p * 8) * N + n0 + bc];
            }
        }
#pragma unroll
        for (int kk = 0; kk < 2; kk++) {
            wmma::fragment<wmma::matrix_a, 16, 16, 8, wmma::precision::tf32, wmma::row_major> af[2];
            wmma::fragment<wmma::matrix_b, 16, 16, 8, wmma::precision::tf32, wmma::row_major> bf[4];
#pragma unroll
            for (int i = 0; i < 2; i++)
                wmma::load_matrix_sync(af[i], &Ash[buf][wm * 32 + 16 * i][kk * 8], 20);
#pragma unroll
            for (int j = 0; j < 4; j++)
                wmma::load_matrix_sync(bf[j], &Bsh[buf][kk * 8][wn * 64 + 16 * j], 132);
#pragma unroll
            for (int i = 0; i < 2; i++)
#pragma unroll
                for (int j = 0; j < 4; j++)
                    wmma::mma_sync(acc[i][j], af[i], bf[j], acc[i][j]);
        }
        if (kt < 63) {
            const int ob = buf ^ 1;
#pragma unroll
            for (int p = 0; p < 2; p++) {
                float* d = &Ash[ob][arow + p * 64][ac];
                d[0] = to_tf32(ra[p].x); d[1] = to_tf32(ra[p].y);
                d[2] = to_tf32(ra[p].z); d[3] = to_tf32(ra[p].w);
                d = &Bsh[ob][brow + p * 8][bc];
                d[0] = to_tf32(rb[p].x); d[1] = to_tf32(rb[p].y);
                d[2] = to_tf32(rb[p].z); d[3] = to_tf32(rb[p].w);
            }
        }
        __syncthreads();
        buf ^= 1;
    }

#pragma unroll
    for (int i = 0; i < 2; i++)
#pragma unroll
        for (int j = 0; j < 4; j++)
            wmma::store_matrix_sync(
                &C[(size_t)(m0 + wm * 32 + 16 * i) * N + n0 + wn * 64 + 16 * j],
                acc[i][j], N, wmma::mem_row_major);
}

// ================= FA2-style attention: register-resident S/P =================
// 128 threads (4 warps), BQ=64 (warp w owns rows w*16..+15), BK=64.
// QK^T: mma.m16n8k8.tf32 (C in regs). Softmax in regs. P->f16 (layout identity).
// PV: mma.m16n8k16.f16 with V via ldmatrix.x2.trans. 2 barriers per k-tile.

__device__ __forceinline__ void mma_tf32_16x8x8(
    float& c0, float& c1, float& c2, float& c3,
    uint32_t a0, uint32_t a1, uint32_t a2, uint32_t a3,
    uint32_t b0, uint32_t b1) {
    asm volatile(
        "mma.sync.aligned.m16n8k8.row.col.f32.tf32.tf32.f32 "
        "{%0,%1,%2,%3}, {%4,%5,%6,%7}, {%8,%9}, {%0,%1,%2,%3};"
        : "+f"(c0), "+f"(c1), "+f"(c2), "+f"(c3)
        : "r"(a0), "r"(a1), "r"(a2), "r"(a3), "r"(b0), "r"(b1));
}
__device__ __forceinline__ void mma_f16_16x8x16(
    float& c0, float& c1, float& c2, float& c3,
    uint32_t a0, uint32_t a1, uint32_t a2, uint32_t a3,
    uint32_t b0, uint32_t b1) {
    asm volatile(
        "mma.sync.aligned.m16n8k16.row.col.f32.f16.f16.f32 "
        "{%0,%1,%2,%3}, {%4,%5,%6,%7}, {%8,%9}, {%0,%1,%2,%3};"
        : "+f"(c0), "+f"(c1), "+f"(c2), "+f"(c3)
        : "r"(a0), "r"(a1), "r"(a2), "r"(a3), "r"(b0), "r"(b1));
}
__device__ __forceinline__ void ldmat_x2_trans(uint32_t& d0, uint32_t& d1, uint32_t saddr) {
    asm volatile("ldmatrix.sync.aligned.m8n8.x2.trans.shared.b16 {%0,%1}, [%2];"
                 : "=r"(d0), "=r"(d1) : "r"(saddr));
}
__device__ __forceinline__ uint32_t pack_h2(float lo, float hi) {
    __half2 h = __floats2half2_rn(lo, hi);
    uint32_t u;
    memcpy(&u, &h, 4);
    return u;
}

#define ALD 68   // float stride for Q,K smem rows
#define VLD 72   // half stride for V smem rows

__global__ __launch_bounds__(128, 4) void attn_kernel() {
    __shared__ float  Qs[64][ALD];
    __shared__ float  Ks[64][ALD];
    __shared__ __half Vs[64][VLD];

    const int t    = threadIdx.x;
    const int lane = t & 31;
    const int w    = t >> 5;                              // warp 0..3
    const int g    = lane >> 2;                           // 0..7
    const int tc   = lane & 3;                            // quad col id
    const int qt   = (int)gridDim.x - 1 - (int)blockIdx.x; // heavy tiles first
    const int q0   = qt * 64;
    const int h    = blockIdx.y;
    const int b    = blockIdx.z;

    const float* Qp = g_Qp + (size_t)b * SEQ * DMODEL + h * DH;
    const float* Kp = g_Kp + (size_t)b * SEQ * DMODEL + h * DH;
    const float* Vp = g_Vp + (size_t)b * SEQ * DMODEL + h * DH;
    float*       Cp = g_Ctx + (size_t)b * SEQ * DMODEL + h * DH;

    // load Q tile 64x64: scale by 1/sqrt(64), tf32-round once
#pragma unroll
    for (int p = 0; p < 8; p++) {
        int i = t + p * 128;
        int row = i >> 4, c = (i & 15) * 4;
        float4 v = *(const float4*)&Qp[(size_t)(q0 + row) * DMODEL + c];
        float* d = &Qs[row][c];
        d[0] = to_tf32(v.x * 0.125f); d[1] = to_tf32(v.y * 0.125f);
        d[2] = to_tf32(v.z * 0.125f); d[3] = to_tf32(v.w * 0.125f);
    }

    const int r0 = w * 16 + g;       // local q-row for c0/c1
    const int r1 = r0 + 8;           // local q-row for c2/c3

    float Oc[8][4];
#pragma unroll
    for (int nb = 0; nb < 8; nb++)
#pragma unroll
        for (int j = 0; j < 4; j++) Oc[nb][j] = 0.0f;
    float m0 = -INFINITY, m1 = -INFINITY, l0 = 0.0f, l1 = 0.0f;

    const uint32_t vbase = (uint32_t)__cvta_generic_to_shared(&Vs[0][0]);
    const uint32_t vlane = vbase + (uint32_t)((lane & 15) * VLD) * 2u;

    for (int kt = 0; kt <= qt; kt++) {
        const int k0 = kt * 64;
        __syncthreads();   // prior iteration's Ks/Vs reads complete
        // load K (tf32 f32) and V (f16) tiles 64x64
#pragma unroll
        for (int p = 0; p < 8; p++) {
            int i = t + p * 128;
            int row = i >> 4, c = (i & 15) * 4;
            float4 vk = *(const float4*)&Kp[(size_t)(k0 + row) * DMODEL + c];
            float4 vv = *(const float4*)&Vp[(size_t)(k0 + row) * DMODEL + c];
            float* dk = &Ks[row][c];
            dk[0] = to_tf32(vk.x); dk[1] = to_tf32(vk.y);
            dk[2] = to_tf32(vk.z); dk[3] = to_tf32(vk.w);
            *(__half2*)&Vs[row][c]     = __floats2half2_rn(vv.x, vv.y);
            *(__half2*)&Vs[row][c + 2] = __floats2half2_rn(vv.z, vv.w);
        }
        __syncthreads();   // Ks/Vs visible

        // ---- S = Q*K^T in registers: 8 k-steps x 8 n-blocks of m16n8k8 ----
        float Sc[8][4];
#pragma unroll
        for (int nb = 0; nb < 8; nb++)
#pragma unroll
            for (int j = 0; j < 4; j++) Sc[nb][j] = 0.0f;

#pragma unroll
        for (int ks = 0; ks < 8; ks++) {
            const int kc = ks * 8 + tc;
            uint32_t a0 = __float_as_uint(Qs[r0][kc]);
            uint32_t a1 = __float_as_uint(Qs[r1][kc]);
            uint32_t a2 = __float_as_uint(Qs[r0][kc + 4]);
            uint32_t a3 = __float_as_uint(Qs[r1][kc + 4]);
#pragma unroll
            for (int nb = 0; nb < 8; nb++) {
                uint32_t b0 = __float_as_uint(Ks[nb * 8 + g][kc]);
                uint32_t b1 = __float_as_uint(Ks[nb * 8 + g][kc + 4]);
                mma_tf32_16x8x8(Sc[nb][0], Sc[nb][1], Sc[nb][2], Sc[nb][3],
                                a0, a1, a2, a3, b0, b1);
            }
        }

        // ---- causal mask (diagonal tile only; k0 == q0 there) ----
        if (kt == qt) {
#pragma unroll
            for (int nb = 0; nb < 8; nb++) {
                int c0 = nb * 8 + tc * 2, c1 = c0 + 1;
                if (c0 > r0) Sc[nb][0] = -INFINITY;
                if (c1 > r0) Sc[nb][1] = -INFINITY;
                if (c0 > r1) Sc[nb][2] = -INFINITY;
                if (c1 > r1) Sc[nb][3] = -INFINITY;
            }
        }

        // ---- online softmax in registers (2 rows per thread) ----
        float mx0 = -INFINITY, mx1 = -INFINITY;
#pragma unroll
        for (int nb = 0; nb < 8; nb++) {
            mx0 = fmaxf(mx0, fmaxf(Sc[nb][0], Sc[nb][1]));
            mx1 = fmaxf(mx1, fmaxf(Sc[nb][2], Sc[nb][3]));
        }
        mx0 = fmaxf(mx0, __shfl_xor_sync(0xffffffffu, mx0, 1));
        mx0 = fmaxf(mx0, __shfl_xor_sync(0xffffffffu, mx0, 2));
        mx1 = fmaxf(mx1, __shfl_xor_sync(0xffffffffu, mx1, 1));
        mx1 = fmaxf(mx1, __shfl_xor_sync(0xffffffffu, mx1, 2));
        const float mn0 = fmaxf(m0, mx0);
        const float mn1 = fmaxf(m1, mx1);
        float sum0 = 0.0f, sum1 = 0.0f;
#pragma unroll
        for (int nb = 0; nb < 8; nb++) {
            Sc[nb][0] = __expf(Sc[nb][0] - mn0);
            Sc[nb][1] = __expf(Sc[nb][1] - mn0);
            Sc[nb][2] = __expf(Sc[nb][2] - mn1);
            Sc[nb][3] = __expf(Sc[nb][3] - mn1);
            sum0 += Sc[nb][0] + Sc[nb][1];
            sum1 += Sc[nb][2] + Sc[nb][3];
        }
        sum0 += __shfl_xor_sync(0xffffffffu, sum0, 1);
        sum0 += __shfl_xor_sync(0xffffffffu, sum0, 2);
        sum1 += __shfl_xor_sync(0xffffffffu, sum1, 1);
        sum1 += __shfl_xor_sync(0xffffffffu, sum1, 2);
        const float a0s = __expf(m0 - mn0);   // 0 on first tile
        const float a1s = __expf(m1 - mn1);
        l0 = l0 * a0s + sum0;  m0 = mn0;
        l1 = l1 * a1s + sum1;  m1 = mn1;
#pragma unroll
        for (int nb = 0; nb < 8; nb++) {
            Oc[nb][0] *= a0s; Oc[nb][1] *= a0s;
            Oc[nb][2] *= a1s; Oc[nb][3] *= a1s;
        }

        // ---- PV: P (regs, f16) x V (smem f16 via ldmatrix.trans) ----
#pragma unroll
        for (int tb = 0; tb < 4; tb++) {
            // m16n8 C-fragment pairs -> m16n8k16 f16 A-fragment (layout identity)
            uint32_t pa0 = pack_h2(Sc[2 * tb][0],     Sc[2 * tb][1]);
            uint32_t pa1 = pack_h2(Sc[2 * tb][2],     Sc[2 * tb][3]);
            uint32_t pa2 = pack_h2(Sc[2 * tb + 1][0], Sc[2 * tb + 1][1]);
            uint32_t pa3 = pack_h2(Sc[2 * tb + 1][2], Sc[2 * tb + 1][3]);
            const uint32_t vrow = vlane + (uint32_t)(tb * 16 * VLD) * 2u;
#pragma unroll
            for (int nb = 0; nb < 8; nb++) {
                uint32_t b0, b1;
                ldmat_x2_trans(b0, b1, vrow + (uint32_t)(nb * 8) * 2u);
                mma_f16_16x8x16(Oc[nb][0], Oc[nb][1], Oc[nb][2], Oc[nb][3],
                                pa0, pa1, pa2, pa3, b0, b1);
            }
        }
    }

    // ---- epilogue: normalize, write context ----
    const float inv0 = 1.0f / l0;
    const float inv1 = 1.0f / l1;
#pragma unroll
    for (int nb = 0; nb < 8; nb++) {
        float2 v0 = make_float2(Oc[nb][0] * inv0, Oc[nb][1] * inv0);
        float2 v1 = make_float2(Oc[nb][2] * inv1, Oc[nb][3] * inv1);
        *(float2*)&Cp[(size_t)(q0 + r0) * DMODEL + nb * 8 + tc * 2] = v0;
        *(float2*)&Cp[(size_t)(q0 + r1) * DMODEL + nb * 8 + tc * 2] = v1;
    }
}

// ---------------- launcher ----------------
extern "C" void kernel_launch(void* const* d_in, const int* in_sizes, int n_in,
                              void* d_out, int out_size) {
    const float* input_Q = (const float*)d_in[0];
    const float* input_K = (const float*)d_in[1];
    const float* input_V = (const float*)d_in[2];
    // d_in[3] = attn_mask (causal, analytic), d_in[4] = flag
    const float* W_Q = (const float*)d_in[5];
    const float* W_K = (const float*)d_in[6];
    const float* W_V = (const float*)d_in[7];
    const float* W_O = (const float*)d_in[8];
    float* out = (float*)d_out;

    float *qp, *kp, *vp, *cp;
    cudaGetSymbolAddress((void**)&qp, g_Qp);
    cudaGetSymbolAddress((void**)&kp, g_Kp);
    cudaGetSymbolAddress((void**)&vp, g_Vp);
    cudaGetSymbolAddress((void**)&cp, g_Ctx);

    // fused QKV projections: grid.z selects operand trio
    dim3 ggrid(DMODEL / 128, (BATCH * SEQ) / 128, 3);   // (8, 32, 3)
    gemm_tf32<<<ggrid, 256>>>(input_Q, input_K, input_V,
                              W_Q, W_K, W_V,
                              qp, kp, vp);

    dim3 agrid(SEQ / 64, NH, BATCH);                    // (32, 16, 2)
    attn_kernel<<<agrid, 128>>>();

    // output projection
    dim3 ogrid(DMODEL / 128, (BATCH * SEQ) / 128, 1);
    gemm_tf32<<<ogrid, 256>>>(cp, cp, cp, W_O, W_O, W_O, out, out, out);
}

// round 14
// speedup vs baseline: 4.2636x; 2.1499x over previous
#include <cuda_runtime.h>
#include <cuda_bf16.h>
#include <cuda_fp16.h>
#include <mma.h>
#include <math.h>
#include <cstdint>
#include <cstring>

using namespace nvcuda;

#define BATCH   2
#define SEQ     2048
#define DMODEL  1024
#define NH      16
#define DH      64

// ---------------- scratch (allocation-free: __device__ globals) ----------------
__device__ float g_Qp[BATCH * SEQ * DMODEL];
__device__ float g_Kp[BATCH * SEQ * DMODEL];
__device__ float g_Vp[BATCH * SEQ * DMODEL];
__device__ float g_Ctx[BATCH * SEQ * DMODEL];

__device__ __forceinline__ float to_tf32(float x) { return wmma::__float_to_tf32(x); }

// ================= f16 WMMA GEMM: C[4096,1024] = A * B  (f32 accumulate) ======
// f16 mantissa (10 explicit bits) == tf32 mantissa -> same relative precision,
// 2x tensor throughput, half the smem traffic. All operands in-range (N(0,1)).
// 128x128 block tile, 256 threads, 8 warps (4M x 2N), warp tile 32x64.
// K-step 32 (2 kk of k16), double-buffered smem + register-prefetched loads.
#define ALDA 40    // half stride, A smem row (32 + 8 pad)
#define BLDB 136   // half stride, B smem row (128 + 8 pad)

__global__ __launch_bounds__(256, 2) void gemm_f16(
    const float* __restrict__ A0, const float* __restrict__ A1, const float* __restrict__ A2,
    const float* __restrict__ B0, const float* __restrict__ B1, const float* __restrict__ B2,
    float* __restrict__ C0, float* __restrict__ C1, float* __restrict__ C2) {
    const int K = 1024, N = 1024;
    __shared__ __half Ash[2][128][ALDA];
    __shared__ __half Bsh[2][32][BLDB];

    const int z = blockIdx.z;
    const float* A = (z == 0) ? A0 : (z == 1) ? A1 : A2;
    const float* B = (z == 0) ? B0 : (z == 1) ? B1 : B2;
    float*       C = (z == 0) ? C0 : (z == 1) ? C1 : C2;

    const int t   = threadIdx.x;
    const int wid = t >> 5;
    const int wm  = wid & 3;    // 0..3 (M)
    const int wn  = wid >> 2;   // 0..1 (N)
    const int m0  = blockIdx.y * 128;
    const int n0  = blockIdx.x * 128;

    // A chunk: 128 rows x 32 cols f32 -> 1024 float4; this thread does 4
    const int arow = t >> 1;              // 0..127 (two float4 per row: halves p=0,1 add 0/…)
    const int ac4  = (t & 1) * 4;         // 0 or 4, +p adds... (see loop: i-based)
    // B chunk: 32 rows x 128 cols -> 1024 float4
    (void)arow; (void)ac4;

    wmma::fragment<wmma::accumulator, 16, 16, 16, float> acc[2][4];
#pragma unroll
    for (int i = 0; i < 2; i++)
#pragma unroll
        for (int j = 0; j < 4; j++) wmma::fill_fragment(acc[i][j], 0.0f);

    float4 ra[4], rb[4];

    auto stage = [&](int buf) {
#pragma unroll
        for (int p = 0; p < 4; p++) {
            int i = t + p * 256;
            {   // A: row = i>>3, c4 = i&7
                int row = i >> 3, c4 = i & 7;
                __half2* d = (__half2*)&Ash[buf][row][c4 * 4];
                d[0] = __floats2half2_rn(ra[p].x, ra[p].y);
                d[1] = __floats2half2_rn(ra[p].z, ra[p].w);
            }
            {   // B: row = i>>5, c4 = i&31
                int row = i >> 5, c4 = i & 31;
                __half2* d = (__half2*)&Bsh[buf][row][c4 * 4];
                d[0] = __floats2half2_rn(rb[p].x, rb[p].y);
                d[1] = __floats2half2_rn(rb[p].z, rb[p].w);
            }
        }
    };
    auto fetch = [&](int k0) {
#pragma unroll
        for (int p = 0; p < 4; p++) {
            int i = t + p * 256;
            int arw = i >> 3, ac = (i & 7) * 4;
            int brw = i >> 5, bc = (i & 31) * 4;
            ra[p] = *(const float4*)&A[(size_t)(m0 + arw) * K + k0 + ac];
            rb[p] = *(const float4*)&B[(size_t)(k0 + brw) * N + n0 + bc];
        }
    };

    fetch(0);
    stage(0);
    __syncthreads();

    int buf = 0;
    for (int kt = 0; kt < 32; kt++) {
        if (kt < 31) fetch((kt + 1) * 32);
#pragma unroll
        for (int kk = 0; kk < 2; kk++) {
            wmma::fragment<wmma::matrix_a, 16, 16, 16, __half, wmma::row_major> af[2];
            wmma::fragment<wmma::matrix_b, 16, 16, 16, __half, wmma::row_major> bf[4];
#pragma unroll
            for (int i = 0; i < 2; i++)
                wmma::load_matrix_sync(af[i], &Ash[buf][wm * 32 + 16 * i][kk * 16], ALDA);
#pragma unroll
            for (int j = 0; j < 4; j++)
                wmma::load_matrix_sync(bf[j], &Bsh[buf][kk * 16][wn * 64 + 16 * j], BLDB);
#pragma unroll
            for (int i = 0; i < 2; i++)
#pragma unroll
                for (int j = 0; j < 4; j++)
                    wmma::mma_sync(acc[i][j], af[i], bf[j], acc[i][j]);
        }
        if (kt < 31) {
            stage(buf ^ 1);
            __syncthreads();
            buf ^= 1;
        }
    }

#pragma unroll
    for (int i = 0; i < 2; i++)
#pragma unroll
        for (int j = 0; j < 4; j++)
            wmma::store_matrix_sync(
                &C[(size_t)(m0 + wm * 32 + 16 * i) * N + n0 + wn * 64 + 16 * j],
                acc[i][j], N, wmma::mem_row_major);
}

// ================= FA2-style attention (unchanged from R13, passing) ==========
__device__ __forceinline__ void mma_tf32_16x8x8(
    float& c0, float& c1, float& c2, float& c3,
    uint32_t a0, uint32_t a1, uint32_t a2, uint32_t a3,
    uint32_t b0, uint32_t b1) {
    asm volatile(
        "mma.sync.aligned.m16n8k8.row.col.f32.tf32.tf32.f32 "
        "{%0,%1,%2,%3}, {%4,%5,%6,%7}, {%8,%9}, {%0,%1,%2,%3};"
        : "+f"(c0), "+f"(c1), "+f"(c2), "+f"(c3)
        : "r"(a0), "r"(a1), "r"(a2), "r"(a3), "r"(b0), "r"(b1));
}
__device__ __forceinline__ void mma_f16_16x8x16(
    float& c0, float& c1, float& c2, float& c3,
    uint32_t a0, uint32_t a1, uint32_t a2, uint32_t a3,
    uint32_t b0, uint32_t b1) {
    asm volatile(
        "mma.sync.aligned.m16n8k16.row.col.f32.f16.f16.f32 "
        "{%0,%1,%2,%3}, {%4,%5,%6,%7}, {%8,%9}, {%0,%1,%2,%3};"
        : "+f"(c0), "+f"(c1), "+f"(c2), "+f"(c3)
        : "r"(a0), "r"(a1), "r"(a2), "r"(a3), "r"(b0), "r"(b1));
}
__device__ __forceinline__ void ldmat_x2_trans(uint32_t& d0, uint32_t& d1, uint32_t saddr) {
    asm volatile("ldmatrix.sync.aligned.m8n8.x2.trans.shared.b16 {%0,%1}, [%2];"
                 : "=r"(d0), "=r"(d1) : "r"(saddr));
}
__device__ __forceinline__ uint32_t pack_h2(float lo, float hi) {
    __half2 h = __floats2half2_rn(lo, hi);
    uint32_t u;
    memcpy(&u, &h, 4);
    return u;
}

#define ALD 68   // float stride for Q,K smem rows
#define VLD 72   // half stride for V smem rows

__global__ __launch_bounds__(128, 4) void attn_kernel() {
    __shared__ float  Qs[64][ALD];
    __shared__ float  Ks[64][ALD];
    __shared__ __half Vs[64][VLD];

    const int t    = threadIdx.x;
    const int lane = t & 31;
    const int w    = t >> 5;
    const int g    = lane >> 2;
    const int tc   = lane & 3;
    const int qt   = (int)gridDim.x - 1 - (int)blockIdx.x;
    const int q0   = qt * 64;
    const int h    = blockIdx.y;
    const int b    = blockIdx.z;

    const float* Qp = g_Qp + (size_t)b * SEQ * DMODEL + h * DH;
    const float* Kp = g_Kp + (size_t)b * SEQ * DMODEL + h * DH;
    const float* Vp = g_Vp + (size_t)b * SEQ * DMODEL + h * DH;
    float*       Cp = g_Ctx + (size_t)b * SEQ * DMODEL + h * DH;

#pragma unroll
    for (int p = 0; p < 8; p++) {
        int i = t + p * 128;
        int row = i >> 4, c = (i & 15) * 4;
        float4 v = *(const float4*)&Qp[(size_t)(q0 + row) * DMODEL + c];
        float* d = &Qs[row][c];
        d[0] = to_tf32(v.x * 0.125f); d[1] = to_tf32(v.y * 0.125f);
        d[2] = to_tf32(v.z * 0.125f); d[3] = to_tf32(v.w * 0.125f);
    }

    const int r0 = w * 16 + g;
    const int r1 = r0 + 8;

    float Oc[8][4];
#pragma unroll
    for (int nb = 0; nb < 8; nb++)
#pragma unroll
        for (int j = 0; j < 4; j++) Oc[nb][j] = 0.0f;
    float m0 = -INFINITY, m1 = -INFINITY, l0 = 0.0f, l1 = 0.0f;

    const uint32_t vbase = (uint32_t)__cvta_generic_to_shared(&Vs[0][0]);
    const uint32_t vlane = vbase + (uint32_t)((lane & 15) * VLD) * 2u;

    for (int kt = 0; kt <= qt; kt++) {
        const int k0 = kt * 64;
        __syncthreads();
#pragma unroll
        for (int p = 0; p < 8; p++) {
            int i = t + p * 128;
            int row = i >> 4, c = (i & 15) * 4;
            float4 vk = *(const float4*)&Kp[(size_t)(k0 + row) * DMODEL + c];
            float4 vv = *(const float4*)&Vp[(size_t)(k0 + row) * DMODEL + c];
            float* dk = &Ks[row][c];
            dk[0] = to_tf32(vk.x); dk[1] = to_tf32(vk.y);
            dk[2] = to_tf32(vk.z); dk[3] = to_tf32(vk.w);
            *(__half2*)&Vs[row][c]     = __floats2half2_rn(vv.x, vv.y);
            *(__half2*)&Vs[row][c + 2] = __floats2half2_rn(vv.z, vv.w);
        }
        __syncthreads();

        float Sc[8][4];
#pragma unroll
        for (int nb = 0; nb < 8; nb++)
#pragma unroll
            for (int j = 0; j < 4; j++) Sc[nb][j] = 0.0f;

#pragma unroll
        for (int ks = 0; ks < 8; ks++) {
            const int kc = ks * 8 + tc;
            uint32_t a0 = __float_as_uint(Qs[r0][kc]);
            uint32_t a1 = __float_as_uint(Qs[r1][kc]);
            uint32_t a2 = __float_as_uint(Qs[r0][kc + 4]);
            uint32_t a3 = __float_as_uint(Qs[r1][kc + 4]);
#pragma unroll
            for (int nb = 0; nb < 8; nb++) {
                uint32_t b0 = __float_as_uint(Ks[nb * 8 + g][kc]);
                uint32_t b1 = __float_as_uint(Ks[nb * 8 + g][kc + 4]);
                mma_tf32_16x8x8(Sc[nb][0], Sc[nb][1], Sc[nb][2], Sc[nb][3],
                                a0, a1, a2, a3, b0, b1);
            }
        }

        if (kt == qt) {
#pragma unroll
            for (int nb = 0; nb < 8; nb++) {
                int c0 = nb * 8 + tc * 2, c1 = c0 + 1;
                if (c0 > r0) Sc[nb][0] = -INFINITY;
                if (c1 > r0) Sc[nb][1] = -INFINITY;
                if (c0 > r1) Sc[nb][2] = -INFINITY;
                if (c1 > r1) Sc[nb][3] = -INFINITY;
            }
        }

        float mx0 = -INFINITY, mx1 = -INFINITY;
#pragma unroll
        for (int nb = 0; nb < 8; nb++) {
            mx0 = fmaxf(mx0, fmaxf(Sc[nb][0], Sc[nb][1]));
            mx1 = fmaxf(mx1, fmaxf(Sc[nb][2], Sc[nb][3]));
        }
        mx0 = fmaxf(mx0, __shfl_xor_sync(0xffffffffu, mx0, 1));
        mx0 = fmaxf(mx0, __shfl_xor_sync(0xffffffffu, mx0, 2));
        mx1 = fmaxf(mx1, __shfl_xor_sync(0xffffffffu, mx1, 1));
        mx1 = fmaxf(mx1, __shfl_xor_sync(0xffffffffu, mx1, 2));
        const float mn0 = fmaxf(m0, mx0);
        const float mn1 = fmaxf(m1, mx1);
        float sum0 = 0.0f, sum1 = 0.0f;
#pragma unroll
        for (int nb = 0; nb < 8; nb++) {
            Sc[nb][0] = __expf(Sc[nb][0] - mn0);
            Sc[nb][1] = __expf(Sc[nb][1] - mn0);
            Sc[nb][2] = __expf(Sc[nb][2] - mn1);
            Sc[nb][3] = __expf(Sc[nb][3] - mn1);
            sum0 += Sc[nb][0] + Sc[nb][1];
            sum1 += Sc[nb][2] + Sc[nb][3];
        }
        sum0 += __shfl_xor_sync(0xffffffffu, sum0, 1);
        sum0 += __shfl_xor_sync(0xffffffffu, sum0, 2);
        sum1 += __shfl_xor_sync(0xffffffffu, sum1, 1);
        sum1 += __shfl_xor_sync(0xffffffffu, sum1, 2);
        const float a0s = __expf(m0 - mn0);
        const float a1s = __expf(m1 - mn1);
        l0 = l0 * a0s + sum0;  m0 = mn0;
        l1 = l1 * a1s + sum1;  m1 = mn1;
#pragma unroll
        for (int nb = 0; nb < 8; nb++) {
            Oc[nb][0] *= a0s; Oc[nb][1] *= a0s;
            Oc[nb][2] *= a1s; Oc[nb][3] *= a1s;
        }

#pragma unroll
        for (int tb = 0; tb < 4; tb++) {
            uint32_t pa0 = pack_h2(Sc[2 * tb][0],     Sc[2 * tb][1]);
            uint32_t pa1 = pack_h2(Sc[2 * tb][2],     Sc[2 * tb][3]);
            uint32_t pa2 = pack_h2(Sc[2 * tb + 1][0], Sc[2 * tb + 1][1]);
            uint32_t pa3 = pack_h2(Sc[2 * tb + 1][2], Sc[2 * tb + 1][3]);
            const uint32_t vrow = vlane + (uint32_t)(tb * 16 * VLD) * 2u;
#pragma unroll
            for (int nb = 0; nb < 8; nb++) {
                uint32_t b0, b1;
                ldmat_x2_trans(b0, b1, vrow + (uint32_t)(nb * 8) * 2u);
                mma_f16_16x8x16(Oc[nb][0], Oc[nb][1], Oc[nb][2], Oc[nb][3],
                                pa0, pa1, pa2, pa3, b0, b1);
            }
        }
    }

    const float inv0 = 1.0f / l0;
    const float inv1 = 1.0f / l1;
#pragma unroll
    for (int nb = 0; nb < 8; nb++) {
        float2 v0 = make_float2(Oc[nb][0] * inv0, Oc[nb][1] * inv0);
        float2 v1 = make_float2(Oc[nb][2] * inv1, Oc[nb][3] * inv1);
        *(float2*)&Cp[(size_t)(q0 + r0) * DMODEL + nb * 8 + tc * 2] = v0;
        *(float2*)&Cp[(size_t)(q0 + r1) * DMODEL + nb * 8 + tc * 2] = v1;
    }
}

// ---------------- launcher ----------------
extern "C" void kernel_launch(void* const* d_in, const int* in_sizes, int n_in,
                              void* d_out, int out_size) {
    const float* input_Q = (const float*)d_in[0];
    const float* input_K = (const float*)d_in[1];
    const float* input_V = (const float*)d_in[2];
    // d_in[3] = attn_mask (causal, analytic), d_in[4] = flag
    const float* W_Q = (const float*)d_in[5];
    const float* W_K = (const float*)d_in[6];
    const float* W_V = (const float*)d_in[7];
    const float* W_O = (const float*)d_in[8];
    float* out = (float*)d_out;

    float *qp, *kp, *vp, *cp;
    cudaGetSymbolAddress((void**)&qp, g_Qp);
    cudaGetSymbolAddress((void**)&kp, g_Kp);
    cudaGetSymbolAddress((void**)&vp, g_Vp);
    cudaGetSymbolAddress((void**)&cp, g_Ctx);

    // fused QKV projections: grid.z selects operand trio
    dim3 ggrid(DMODEL / 128, (BATCH * SEQ) / 128, 3);   // (8, 32, 3)
    gemm_f16<<<ggrid, 256>>>(input_Q, input_K, input_V,
                             W_Q, W_K, W_V,
                             qp, kp, vp);

    dim3 agrid(SEQ / 64, NH, BATCH);                    // (32, 16, 2)
    attn_kernel<<<agrid, 128>>>();

    // output projection
    dim3 ogrid(DMODEL / 128, (BATCH * SEQ) / 128, 1);
    gemm_f16<<<ogrid, 256>>>(cp, cp, cp, W_O, W_O, W_O, out, out, out);
}

// round 15
// speedup vs baseline: 5.2167x; 1.2236x over previous
#include <cuda_runtime.h>
#include <cuda_bf16.h>
#include <cuda_fp16.h>
#include <mma.h>
#include <math.h>
#include <cstdint>
#include <cstring>

using namespace nvcuda;

#define BATCH   2
#define SEQ     2048
#define DMODEL  1024
#define NH      16
#define DH      64
#define NTOK    (BATCH * SEQ)          // 4096

// ---------------- f16 scratch (allocation-free: __device__ globals) -----------
__device__ __align__(16) __half g_inQ[NTOK * DMODEL];
__device__ __align__(16) __half g_inK[NTOK * DMODEL];
__device__ __align__(16) __half g_inV[NTOK * DMODEL];
__device__ __align__(16) __half g_WQ[DMODEL * DMODEL];   // pre-scaled by 0.125
__device__ __align__(16) __half g_WK[DMODEL * DMODEL];
__device__ __align__(16) __half g_WV[DMODEL * DMODEL];
__device__ __align__(16) __half g_WO[DMODEL * DMODEL];
__device__ __align__(16) __half g_Qh[NTOK * DMODEL];
__device__ __align__(16) __half g_Kh[NTOK * DMODEL];
__device__ __align__(16) __half g_Vh[NTOK * DMODEL];
__device__ __align__(16) __half g_Ctxh[NTOK * DMODEL];

__device__ __forceinline__ uint32_t pack_h2(float lo, float hi) {
    __half2 h = __floats2half2_rn(lo, hi);
    uint32_t u;
    memcpy(&u, &h, 4);
    return u;
}

// ---------------- f32 -> f16 conversion kernels -------------------------------
__global__ __launch_bounds__(256) void cvt_in(
    const float* __restrict__ s0, const float* __restrict__ s1, const float* __restrict__ s2,
    __half* __restrict__ d0, __half* __restrict__ d1, __half* __restrict__ d2) {
    const int z = blockIdx.z;
    const float* s = (z == 0) ? s0 : (z == 1) ? s1 : s2;
    __half*      d = (z == 0) ? d0 : (z == 1) ? d1 : d2;
    const size_t i = (size_t)blockIdx.x * 256 + threadIdx.x;   // float4 index
    float4 v = *(const float4*)&s[i * 4];
    *(__half2*)&d[i * 4]     = __floats2half2_rn(v.x, v.y);
    *(__half2*)&d[i * 4 + 2] = __floats2half2_rn(v.z, v.w);
}

__global__ __launch_bounds__(256) void cvt_w(
    const float* __restrict__ s0, const float* __restrict__ s1,
    const float* __restrict__ s2, const float* __restrict__ s3,
    __half* __restrict__ d0, __half* __restrict__ d1,
    __half* __restrict__ d2, __half* __restrict__ d3) {
    const int z = blockIdx.z;
    const float* s = (z == 0) ? s0 : (z == 1) ? s1 : (z == 2) ? s2 : s3;
    __half*      d = (z == 0) ? d0 : (z == 1) ? d1 : (z == 2) ? d2 : d3;
    const float  sc = (z == 0) ? 0.125f : 1.0f;   // fold 1/sqrt(d_k) into W_Q (exact pow2)
    const size_t i = (size_t)blockIdx.x * 256 + threadIdx.x;
    float4 v = *(const float4*)&s[i * 4];
    *(__half2*)&d[i * 4]     = __floats2half2_rn(v.x * sc, v.y * sc);
    *(__half2*)&d[i * 4 + 2] = __floats2half2_rn(v.z * sc, v.w * sc);
}

// ================= f16-in f16/f32-out WMMA GEMM ==============================
// C[4096,1024] = A[4096,1024] * B[1024,1024], A/B already f16.
// 128x128 block tile, 256 threads, 8 warps (4M x 2N), warp tile 32x64.
// K-step 32, double-buffered smem, plain uint4 staging (no conversion in loop).
#define ALDA 40    // half stride, A smem row (32 + 8 pad)
#define BLDB 136   // half stride, B smem row (128 + 8 pad)

template <typename OutT>
__global__ __launch_bounds__(256, 2) void gemm_h(
    const __half* __restrict__ A0, const __half* __restrict__ A1, const __half* __restrict__ A2,
    const __half* __restrict__ B0, const __half* __restrict__ B1, const __half* __restrict__ B2,
    OutT* __restrict__ C0, OutT* __restrict__ C1, OutT* __restrict__ C2) {
    const int K = 1024, N = 1024;
    __shared__ __half Ash[2][128][ALDA];
    __shared__ __half Bsh[2][32][BLDB];

    const int z = blockIdx.z;
    const __half* A = (z == 0) ? A0 : (z == 1) ? A1 : A2;
    const __half* B = (z == 0) ? B0 : (z == 1) ? B1 : B2;
    OutT*         C = (z == 0) ? C0 : (z == 1) ? C1 : C2;

    const int t   = threadIdx.x;
    const int wid = t >> 5;
    const int lane = t & 31;
    const int wm  = wid & 3;    // 0..3 (M)
    const int wn  = wid >> 2;   // 0..1 (N)
    const int m0  = blockIdx.y * 128;
    const int n0  = blockIdx.x * 128;

    wmma::fragment<wmma::accumulator, 16, 16, 16, float> acc[2][4];
#pragma unroll
    for (int i = 0; i < 2; i++)
#pragma unroll
        for (int j = 0; j < 4; j++) wmma::fill_fragment(acc[i][j], 0.0f);

    uint4 ra[2], rb[2];
    auto fetch = [&](int k0) {
#pragma unroll
        for (int p = 0; p < 2; p++) {
            int i = t + p * 256;
            int arw = i >> 2, ac = (i & 3) * 8;     // A: 128 rows x 32 halves
            int brw = i >> 4, bc = (i & 15) * 8;    // B: 32 rows x 128 halves
            ra[p] = *(const uint4*)&A[(size_t)(m0 + arw) * K + k0 + ac];
            rb[p] = *(const uint4*)&B[(size_t)(k0 + brw) * N + n0 + bc];
        }
    };
    auto stage = [&](int buf) {
#pragma unroll
        for (int p = 0; p < 2; p++) {
            int i = t + p * 256;
            int arw = i >> 2, ac = (i & 3) * 8;
            int brw = i >> 4, bc = (i & 15) * 8;
            *(uint4*)&Ash[buf][arw][ac] = ra[p];
            *(uint4*)&Bsh[buf][brw][bc] = rb[p];
        }
    };

    fetch(0);
    stage(0);
    __syncthreads();

    int buf = 0;
    for (int kt = 0; kt < 32; kt++) {
        if (kt < 31) fetch((kt + 1) * 32);
#pragma unroll
        for (int kk = 0; kk < 2; kk++) {
            wmma::fragment<wmma::matrix_a, 16, 16, 16, __half, wmma::row_major> af[2];
            wmma::fragment<wmma::matrix_b, 16, 16, 16, __half, wmma::row_major> bf[4];
#pragma unroll
            for (int i = 0; i < 2; i++)
                wmma::load_matrix_sync(af[i], &Ash[buf][wm * 32 + 16 * i][kk * 16], ALDA);
#pragma unroll
            for (int j = 0; j < 4; j++)
                wmma::load_matrix_sync(bf[j], &Bsh[buf][kk * 16][wn * 64 + 16 * j], BLDB);
#pragma unroll
            for (int i = 0; i < 2; i++)
#pragma unroll
                for (int j = 0; j < 4; j++)
                    wmma::mma_sync(acc[i][j], af[i], bf[j], acc[i][j]);
        }
        if (kt < 31) {
            stage(buf ^ 1);
            __syncthreads();
            buf ^= 1;
        }
    }

    if constexpr (sizeof(OutT) == 4) {
        // f32 output: direct wmma store
#pragma unroll
        for (int i = 0; i < 2; i++)
#pragma unroll
            for (int j = 0; j < 4; j++)
                wmma::store_matrix_sync(
                    (float*)&C[(size_t)(m0 + wm * 32 + 16 * i) * N + n0 + wn * 64 + 16 * j],
                    acc[i][j], N, wmma::mem_row_major);
    } else {
        // f16 output: per-warp smem patch (16x16 f32, stride 20), then half stores
        __syncthreads();   // all warps done reading smem buffers
        float* patch = reinterpret_cast<float*>(&Ash[0][0][0]) + wid * 320;  // 16*20 f32
        const int prow = lane >> 1;
        const int pcb  = (lane & 1) * 8;
#pragma unroll
        for (int i = 0; i < 2; i++)
#pragma unroll
            for (int j = 0; j < 4; j++) {
                wmma::store_matrix_sync(patch, acc[i][j], 20, wmma::mem_row_major);
                __syncwarp();
                float4 v0 = *(float4*)&patch[prow * 20 + pcb];
                float4 v1 = *(float4*)&patch[prow * 20 + pcb + 4];
                uint4 u;
                u.x = pack_h2(v0.x, v0.y);
                u.y = pack_h2(v0.z, v0.w);
                u.z = pack_h2(v1.x, v1.y);
                u.w = pack_h2(v1.z, v1.w);
                *(uint4*)&C[(size_t)(m0 + wm * 32 + 16 * i + prow) * N +
                            n0 + wn * 64 + 16 * j + pcb] = u;
                __syncwarp();
            }
    }
}

// ================= FA2-style attention, all-f16 operands ======================
// 128 threads (4 warps), BQ=64, BK=64. QK^T: mma.m16n8k16.f16 (Q pre-scaled via
// W_Q). Softmax f32 in regs. PV: f16 mma with V via ldmatrix.x2.trans.
__device__ __forceinline__ void mma_f16_16x8x16(
    float& c0, float& c1, float& c2, float& c3,
    uint32_t a0, uint32_t a1, uint32_t a2, uint32_t a3,
    uint32_t b0, uint32_t b1) {
    asm volatile(
        "mma.sync.aligned.m16n8k16.row.col.f32.f16.f16.f32 "
        "{%0,%1,%2,%3}, {%4,%5,%6,%7}, {%8,%9}, {%0,%1,%2,%3};"
        : "+f"(c0), "+f"(c1), "+f"(c2), "+f"(c3)
        : "r"(a0), "r"(a1), "r"(a2), "r"(a3), "r"(b0), "r"(b1));
}
__device__ __forceinline__ void ldmat_x2_trans(uint32_t& d0, uint32_t& d1, uint32_t saddr) {
    asm volatile("ldmatrix.sync.aligned.m8n8.x2.trans.shared.b16 {%0,%1}, [%2];"
                 : "=r"(d0), "=r"(d1) : "r"(saddr));
}

#define QLD 72   // half stride for Q/K/V smem rows

__global__ __launch_bounds__(128, 4) void attn_kernel() {
    __shared__ __half Qs[64][QLD];
    __shared__ __half Ks[64][QLD];
    __shared__ __half Vs[64][QLD];

    const int t    = threadIdx.x;
    const int lane = t & 31;
    const int w    = t >> 5;
    const int g    = lane >> 2;
    const int tc   = lane & 3;
    const int qt   = (int)gridDim.x - 1 - (int)blockIdx.x;   // heavy tiles first
    const int q0   = qt * 64;
    const int h    = blockIdx.y;
    const int b    = blockIdx.z;

    const __half* Qp = g_Qh + (size_t)b * SEQ * DMODEL + h * DH;
    const __half* Kp = g_Kh + (size_t)b * SEQ * DMODEL + h * DH;
    const __half* Vp = g_Vh + (size_t)b * SEQ * DMODEL + h * DH;
    __half*       Cp = g_Ctxh + (size_t)b * SEQ * DMODEL + h * DH;

    // load Q tile 64x64 halves (Q already scaled by 1/8 via W_Q)
#pragma unroll
    for (int p = 0; p < 4; p++) {
        int i = t + p * 128;
        int row = i >> 3, c = (i & 7) * 8;
        *(uint4*)&Qs[row][c] = *(const uint4*)&Qp[(size_t)(q0 + row) * DMODEL + c];
    }

    const int r0 = w * 16 + g;
    const int r1 = r0 + 8;

    float Oc[8][4];
#pragma unroll
    for (int nb = 0; nb < 8; nb++)
#pragma unroll
        for (int j = 0; j < 4; j++) Oc[nb][j] = 0.0f;
    float m0 = -INFINITY, m1 = -INFINITY, l0 = 0.0f, l1 = 0.0f;

    const uint32_t vbase = (uint32_t)__cvta_generic_to_shared(&Vs[0][0]);
    const uint32_t vlane = vbase + (uint32_t)((lane & 15) * QLD) * 2u;

    for (int kt = 0; kt <= qt; kt++) {
        const int k0 = kt * 64;
        __syncthreads();
#pragma unroll
        for (int p = 0; p < 4; p++) {
            int i = t + p * 128;
            int row = i >> 3, c = (i & 7) * 8;
            *(uint4*)&Ks[row][c] = *(const uint4*)&Kp[(size_t)(k0 + row) * DMODEL + c];
            *(uint4*)&Vs[row][c] = *(const uint4*)&Vp[(size_t)(k0 + row) * DMODEL + c];
        }
        __syncthreads();

        // ---- S = Q*K^T : 4 k16-steps x 8 n-blocks, all f16 ----
        float Sc[8][4];
#pragma unroll
        for (int nb = 0; nb < 8; nb++)
#pragma unroll
            for (int j = 0; j < 4; j++) Sc[nb][j] = 0.0f;

#pragma unroll
        for (int ks = 0; ks < 4; ks++) {
            const int kb = ks * 16 + 2 * tc;
            uint32_t a0 = *(const uint32_t*)&Qs[r0][kb];
            uint32_t a1 = *(const uint32_t*)&Qs[r1][kb];
            uint32_t a2 = *(const uint32_t*)&Qs[r0][kb + 8];
            uint32_t a3 = *(const uint32_t*)&Qs[r1][kb + 8];
#pragma unroll
            for (int nb = 0; nb < 8; nb++) {
                uint32_t b0 = *(const uint32_t*)&Ks[nb * 8 + g][kb];
                uint32_t b1 = *(const uint32_t*)&Ks[nb * 8 + g][kb + 8];
                mma_f16_16x8x16(Sc[nb][0], Sc[nb][1], Sc[nb][2], Sc[nb][3],
                                a0, a1, a2, a3, b0, b1);
            }
        }

        // ---- causal mask (diagonal tile only) ----
        if (kt == qt) {
#pragma unroll
            for (int nb = 0; nb < 8; nb++) {
                int c0 = nb * 8 + tc * 2, c1 = c0 + 1;
                if (c0 > r0) Sc[nb][0] = -INFINITY;
                if (c1 > r0) Sc[nb][1] = -INFINITY;
                if (c0 > r1) Sc[nb][2] = -INFINITY;
                if (c1 > r1) Sc[nb][3] = -INFINITY;
            }
        }

        // ---- online softmax in registers ----
        float mx0 = -INFINITY, mx1 = -INFINITY;
#pragma unroll
        for (int nb = 0; nb < 8; nb++) {
            mx0 = fmaxf(mx0, fmaxf(Sc[nb][0], Sc[nb][1]));
            mx1 = fmaxf(mx1, fmaxf(Sc[nb][2], Sc[nb][3]));
        }
        mx0 = fmaxf(mx0, __shfl_xor_sync(0xffffffffu, mx0, 1));
        mx0 = fmaxf(mx0, __shfl_xor_sync(0xffffffffu, mx0, 2));
        mx1 = fmaxf(mx1, __shfl_xor_sync(0xffffffffu, mx1, 1));
        mx1 = fmaxf(mx1, __shfl_xor_sync(0xffffffffu, mx1, 2));
        const float mn0 = fmaxf(m0, mx0);
        const float mn1 = fmaxf(m1, mx1);
        float sum0 = 0.0f, sum1 = 0.0f;
#pragma unroll
        for (int nb = 0; nb < 8; nb++) {
            Sc[nb][0] = __expf(Sc[nb][0] - mn0);
            Sc[nb][1] = __expf(Sc[nb][1] - mn0);
            Sc[nb][2] = __expf(Sc[nb][2] - mn1);
            Sc[nb][3] = __expf(Sc[nb][3] - mn1);
            sum0 += Sc[nb][0] + Sc[nb][1];
            sum1 += Sc[nb][2] + Sc[nb][3];
        }
        sum0 += __shfl_xor_sync(0xffffffffu, sum0, 1);
        sum0 += __shfl_xor_sync(0xffffffffu, sum0, 2);
        sum1 += __shfl_xor_sync(0xffffffffu, sum1, 1);
        sum1 += __shfl_xor_sync(0xffffffffu, sum1, 2);
        const float a0s = __expf(m0 - mn0);   // 0 on first tile
        const float a1s = __expf(m1 - mn1);
        l0 = l0 * a0s + sum0;  m0 = mn0;
        l1 = l1 * a1s + sum1;  m1 = mn1;
#pragma unroll
        for (int nb = 0; nb < 8; nb++) {
            Oc[nb][0] *= a0s; Oc[nb][1] *= a0s;
            Oc[nb][2] *= a1s; Oc[nb][3] *= a1s;
        }

        // ---- PV: P (regs -> f16) x V (smem f16 via ldmatrix.trans) ----
#pragma unroll
        for (int tb = 0; tb < 4; tb++) {
            uint32_t pa0 = pack_h2(Sc[2 * tb][0],     Sc[2 * tb][1]);
            uint32_t pa1 = pack_h2(Sc[2 * tb][2],     Sc[2 * tb][3]);
            uint32_t pa2 = pack_h2(Sc[2 * tb + 1][0], Sc[2 * tb + 1][1]);
            uint32_t pa3 = pack_h2(Sc[2 * tb + 1][2], Sc[2 * tb + 1][3]);
            const uint32_t vrow = vlane + (uint32_t)(tb * 16 * QLD) * 2u;
#pragma unroll
            for (int nb = 0; nb < 8; nb++) {
                uint32_t b0, b1;
                ldmat_x2_trans(b0, b1, vrow + (uint32_t)(nb * 8) * 2u);
                mma_f16_16x8x16(Oc[nb][0], Oc[nb][1], Oc[nb][2], Oc[nb][3],
                                pa0, pa1, pa2, pa3, b0, b1);
            }
        }
    }

    // ---- epilogue: normalize, write context as f16 ----
    const float inv0 = 1.0f / l0;
    const float inv1 = 1.0f / l1;
#pragma unroll
    for (int nb = 0; nb < 8; nb++) {
        *(__half2*)&Cp[(size_t)(q0 + r0) * DMODEL + nb * 8 + tc * 2] =
            __floats2half2_rn(Oc[nb][0] * inv0, Oc[nb][1] * inv0);
        *(__half2*)&Cp[(size_t)(q0 + r1) * DMODEL + nb * 8 + tc * 2] =
            __floats2half2_rn(Oc[nb][2] * inv1, Oc[nb][3] * inv1);
    }
}

// ---------------- launcher ----------------
extern "C" void kernel_launch(void* const* d_in, const int* in_sizes, int n_in,
                              void* d_out, int out_size) {
    const float* input_Q = (const float*)d_in[0];
    const float* input_K = (const float*)d_in[1];
    const float* input_V = (const float*)d_in[2];
    // d_in[3] = attn_mask (causal, analytic), d_in[4] = flag
    const float* W_Q = (const float*)d_in[5];
    const float* W_K = (const float*)d_in[6];
    const float* W_V = (const float*)d_in[7];
    const float* W_O = (const float*)d_in[8];
    float* out = (float*)d_out;

    __half *inq, *ink, *inv, *wq, *wk, *wv, *wo, *qh, *kh, *vh, *ch;
    cudaGetSymbolAddress((void**)&inq, g_inQ);
    cudaGetSymbolAddress((void**)&ink, g_inK);
    cudaGetSymbolAddress((void**)&inv, g_inV);
    cudaGetSymbolAddress((void**)&wq, g_WQ);
    cudaGetSymbolAddress((void**)&wk, g_WK);
    cudaGetSymbolAddress((void**)&wv, g_WV);
    cudaGetSymbolAddress((void**)&wo, g_WO);
    cudaGetSymbolAddress((void**)&qh, g_Qh);
    cudaGetSymbolAddress((void**)&kh, g_Kh);
    cudaGetSymbolAddress((void**)&vh, g_Vh);
    cudaGetSymbolAddress((void**)&ch, g_Ctxh);

    // 1) convert inputs + weights to f16 (W_Q folded with 1/sqrt(d_k))
    dim3 cgrid_in(NTOK * DMODEL / 4 / 256, 1, 3);    // (4096,1,3)
    cvt_in<<<cgrid_in, 256>>>(input_Q, input_K, input_V, inq, ink, inv);
    dim3 cgrid_w(DMODEL * DMODEL / 4 / 256, 1, 4);   // (1024,1,4)
    cvt_w<<<cgrid_w, 256>>>(W_Q, W_K, W_V, W_O, wq, wk, wv, wo);

    // 2) fused QKV projections (f16 in, f16 out)
    dim3 ggrid(DMODEL / 128, NTOK / 128, 3);         // (8, 32, 3)
    gemm_h<__half><<<ggrid, 256>>>(inq, ink, inv, wq, wk, wv, qh, kh, vh);

    // 3) attention (all f16 operands)
    dim3 agrid(SEQ / 64, NH, BATCH);                 // (32, 16, 2)
    attn_kernel<<<agrid, 128>>>();

    // 4) output projection (f16 in, f32 out)
    dim3 ogrid(DMODEL / 128, NTOK / 128, 1);
    gemm_h<float><<<ogrid, 256>>>(ch, ch, ch, wo, wo, wo, out, out, out);
}

// round 16
// speedup vs baseline: 5.6441x; 1.0819x over previous
#include <cuda_runtime.h>
#include <cuda_bf16.h>
#include <cuda_fp16.h>
#include <mma.h>
#include <math.h>
#include <cstdint>
#include <cstring>

using namespace nvcuda;

#define BATCH   2
#define SEQ     2048
#define DMODEL  1024
#define NH      16
#define DH      64
#define NTOK    (BATCH * SEQ)          // 4096

// ---------------- f16 scratch (allocation-free: __device__ globals) -----------
__device__ __align__(16) __half g_inQ[NTOK * DMODEL];
__device__ __align__(16) __half g_inK[NTOK * DMODEL];
__device__ __align__(16) __half g_inV[NTOK * DMODEL];
__device__ __align__(16) __half g_WQ[DMODEL * DMODEL];   // pre-scaled by 0.125
__device__ __align__(16) __half g_WK[DMODEL * DMODEL];
__device__ __align__(16) __half g_WV[DMODEL * DMODEL];
__device__ __align__(16) __half g_WO[DMODEL * DMODEL];
__device__ __align__(16) __half g_Qh[NTOK * DMODEL];
__device__ __align__(16) __half g_Kh[NTOK * DMODEL];
__device__ __align__(16) __half g_Vh[NTOK * DMODEL];
__device__ __align__(16) __half g_Ctxh[NTOK * DMODEL];

__device__ __forceinline__ uint32_t pack_h2(float lo, float hi) {
    __half2 h = __floats2half2_rn(lo, hi);
    uint32_t u;
    memcpy(&u, &h, 4);
    return u;
}
__device__ __forceinline__ void cp_async16(uint32_t saddr, const void* g) {
    asm volatile("cp.async.cg.shared.global [%0], [%1], 16;" :: "r"(saddr), "l"(g));
}
#define CP_COMMIT() asm volatile("cp.async.commit_group;" ::: "memory")
#define CP_WAIT(n)  asm volatile("cp.async.wait_group %0;" :: "n"(n) : "memory")

// ---------------- f32 -> f16 conversion kernels -------------------------------
__global__ __launch_bounds__(256) void cvt_in(
    const float* __restrict__ s0, const float* __restrict__ s1, const float* __restrict__ s2,
    __half* __restrict__ d0, __half* __restrict__ d1, __half* __restrict__ d2) {
    const int z = blockIdx.z;
    const float* s = (z == 0) ? s0 : (z == 1) ? s1 : s2;
    __half*      d = (z == 0) ? d0 : (z == 1) ? d1 : d2;
    const size_t i = (size_t)blockIdx.x * 256 + threadIdx.x;
    float4 v = *(const float4*)&s[i * 4];
    *(__half2*)&d[i * 4]     = __floats2half2_rn(v.x, v.y);
    *(__half2*)&d[i * 4 + 2] = __floats2half2_rn(v.z, v.w);
}

__global__ __launch_bounds__(256) void cvt_w(
    const float* __restrict__ s0, const float* __restrict__ s1,
    const float* __restrict__ s2, const float* __restrict__ s3,
    __half* __restrict__ d0, __half* __restrict__ d1,
    __half* __restrict__ d2, __half* __restrict__ d3) {
    const int z = blockIdx.z;
    const float* s = (z == 0) ? s0 : (z == 1) ? s1 : (z == 2) ? s2 : s3;
    __half*      d = (z == 0) ? d0 : (z == 1) ? d1 : (z == 2) ? d2 : d3;
    const float  sc = (z == 0) ? 0.125f : 1.0f;   // fold 1/sqrt(d_k) into W_Q
    const size_t i = (size_t)blockIdx.x * 256 + threadIdx.x;
    float4 v = *(const float4*)&s[i * 4];
    *(__half2*)&d[i * 4]     = __floats2half2_rn(v.x * sc, v.y * sc);
    *(__half2*)&d[i * 4 + 2] = __floats2half2_rn(v.z * sc, v.w * sc);
}

// ================= f16 WMMA GEMM with cp.async double buffering ==============
// C[4096,1024] = A * B, f16 inputs. 128x128 tile, 256 thr, 8 warps (4M x 2N).
#define ALDA 40    // half stride, A smem row (32 + 8 pad)
#define BLDB 136   // half stride, B smem row (128 + 8 pad)

template <typename OutT>
__global__ __launch_bounds__(256, 2) void gemm_h(
    const __half* __restrict__ A0, const __half* __restrict__ A1, const __half* __restrict__ A2,
    const __half* __restrict__ B0, const __half* __restrict__ B1, const __half* __restrict__ B2,
    OutT* __restrict__ C0, OutT* __restrict__ C1, OutT* __restrict__ C2) {
    const int K = 1024, N = 1024;
    __shared__ __half Ash[2][128][ALDA];
    __shared__ __half Bsh[2][32][BLDB];

    const int z = blockIdx.z;
    const __half* A = (z == 0) ? A0 : (z == 1) ? A1 : A2;
    const __half* B = (z == 0) ? B0 : (z == 1) ? B1 : B2;
    OutT*         C = (z == 0) ? C0 : (z == 1) ? C1 : C2;

    const int t    = threadIdx.x;
    const int wid  = t >> 5;
    const int lane = t & 31;
    const int wm   = wid & 3;
    const int wn   = wid >> 2;
    const int m0   = blockIdx.y * 128;
    const int n0   = blockIdx.x * 128;

    const uint32_t sA = (uint32_t)__cvta_generic_to_shared(&Ash[0][0][0]);
    const uint32_t sB = (uint32_t)__cvta_generic_to_shared(&Bsh[0][0][0]);

    wmma::fragment<wmma::accumulator, 16, 16, 16, float> acc[2][4];
#pragma unroll
    for (int i = 0; i < 2; i++)
#pragma unroll
        for (int j = 0; j < 4; j++) wmma::fill_fragment(acc[i][j], 0.0f);

    auto issue = [&](int k0, int buf) {
#pragma unroll
        for (int p = 0; p < 2; p++) {
            int i = t + p * 256;
            int arw = i >> 2, ac = (i & 3) * 8;     // A: 128 rows x 32 halves
            int brw = i >> 4, bc = (i & 15) * 8;    // B: 32 rows x 128 halves
            cp_async16(sA + (uint32_t)(((buf * 128 + arw) * ALDA + ac) * 2),
                       &A[(size_t)(m0 + arw) * K + k0 + ac]);
            cp_async16(sB + (uint32_t)(((buf * 32 + brw) * BLDB + bc) * 2),
                       &B[(size_t)(k0 + brw) * N + n0 + bc]);
        }
    };

    issue(0, 0);
    CP_COMMIT();

    int buf = 0;
    for (int kt = 0; kt < 32; kt++) {
        __syncthreads();            // all reads of buf^1 (iter kt-1) complete
        if (kt < 31) {
            issue((kt + 1) * 32, buf ^ 1);
            CP_COMMIT();
            CP_WAIT(1);             // tile kt arrived
        } else {
            CP_WAIT(0);
        }
        __syncthreads();            // tile kt visible to all warps
#pragma unroll
        for (int kk = 0; kk < 2; kk++) {
            wmma::fragment<wmma::matrix_a, 16, 16, 16, __half, wmma::row_major> af[2];
            wmma::fragment<wmma::matrix_b, 16, 16, 16, __half, wmma::row_major> bf[4];
#pragma unroll
            for (int i = 0; i < 2; i++)
                wmma::load_matrix_sync(af[i], &Ash[buf][wm * 32 + 16 * i][kk * 16], ALDA);
#pragma unroll
            for (int j = 0; j < 4; j++)
                wmma::load_matrix_sync(bf[j], &Bsh[buf][kk * 16][wn * 64 + 16 * j], BLDB);
#pragma unroll
            for (int i = 0; i < 2; i++)
#pragma unroll
                for (int j = 0; j < 4; j++)
                    wmma::mma_sync(acc[i][j], af[i], bf[j], acc[i][j]);
        }
        buf ^= 1;
    }

    if constexpr (sizeof(OutT) == 4) {
#pragma unroll
        for (int i = 0; i < 2; i++)
#pragma unroll
            for (int j = 0; j < 4; j++)
                wmma::store_matrix_sync(
                    (float*)&C[(size_t)(m0 + wm * 32 + 16 * i) * N + n0 + wn * 64 + 16 * j],
                    acc[i][j], N, wmma::mem_row_major);
    } else {
        __syncthreads();   // smem buffers free for reuse as patch space
        float* patch = reinterpret_cast<float*>(&Ash[0][0][0]) + wid * 320;  // 16x16 f32 @ stride 20
        const int prow = lane >> 1;
        const int pcb  = (lane & 1) * 8;
#pragma unroll
        for (int i = 0; i < 2; i++)
#pragma unroll
            for (int j = 0; j < 4; j++) {
                wmma::store_matrix_sync(patch, acc[i][j], 20, wmma::mem_row_major);
                __syncwarp();
                float4 v0 = *(float4*)&patch[prow * 20 + pcb];
                float4 v1 = *(float4*)&patch[prow * 20 + pcb + 4];
                uint4 u;
                u.x = pack_h2(v0.x, v0.y);
                u.y = pack_h2(v0.z, v0.w);
                u.z = pack_h2(v1.x, v1.y);
                u.w = pack_h2(v1.z, v1.w);
                *(uint4*)&C[(size_t)(m0 + wm * 32 + 16 * i + prow) * N +
                            n0 + wn * 64 + 16 * j + pcb] = u;
                __syncwarp();
            }
    }
}

// ================= FA2 attention: cp.async K/V pipeline + hoisted Q frags =====
__device__ __forceinline__ void mma_f16_16x8x16(
    float& c0, float& c1, float& c2, float& c3,
    uint32_t a0, uint32_t a1, uint32_t a2, uint32_t a3,
    uint32_t b0, uint32_t b1) {
    asm volatile(
        "mma.sync.aligned.m16n8k16.row.col.f32.f16.f16.f32 "
        "{%0,%1,%2,%3}, {%4,%5,%6,%7}, {%8,%9}, {%0,%1,%2,%3};"
        : "+f"(c0), "+f"(c1), "+f"(c2), "+f"(c3)
        : "r"(a0), "r"(a1), "r"(a2), "r"(a3), "r"(b0), "r"(b1));
}
__device__ __forceinline__ void ldmat_x2_trans(uint32_t& d0, uint32_t& d1, uint32_t saddr) {
    asm volatile("ldmatrix.sync.aligned.m8n8.x2.trans.shared.b16 {%0,%1}, [%2];"
                 : "=r"(d0), "=r"(d1) : "r"(saddr));
}

#define QLD 72   // half stride for K/V smem rows (64 + 8 pad; 144B = 9*16)

__global__ __launch_bounds__(128, 4) void attn_kernel() {
    __shared__ __half Ks[2][64][QLD];
    __shared__ __half Vs[2][64][QLD];

    const int t    = threadIdx.x;
    const int lane = t & 31;
    const int w    = t >> 5;
    const int g    = lane >> 2;
    const int tc   = lane & 3;
    const int qt   = (int)gridDim.x - 1 - (int)blockIdx.x;   // heavy tiles first
    const int q0   = qt * 64;
    const int h    = blockIdx.y;
    const int b    = blockIdx.z;

    const __half* Qp = g_Qh + (size_t)b * SEQ * DMODEL + h * DH;
    const __half* Kp = g_Kh + (size_t)b * SEQ * DMODEL + h * DH;
    const __half* Vp = g_Vh + (size_t)b * SEQ * DMODEL + h * DH;
    __half*       Cp = g_Ctxh + (size_t)b * SEQ * DMODEL + h * DH;

    const int r0 = w * 16 + g;
    const int r1 = r0 + 8;

    // ---- hoisted Q fragments: loop-invariant, loaded once from gmem ----
    uint32_t qa[4][4];
#pragma unroll
    for (int ks = 0; ks < 4; ks++) {
        const int kb = ks * 16 + 2 * tc;
        qa[ks][0] = *(const uint32_t*)&Qp[(size_t)(q0 + r0) * DMODEL + kb];
        qa[ks][1] = *(const uint32_t*)&Qp[(size_t)(q0 + r1) * DMODEL + kb];
        qa[ks][2] = *(const uint32_t*)&Qp[(size_t)(q0 + r0) * DMODEL + kb + 8];
        qa[ks][3] = *(const uint32_t*)&Qp[(size_t)(q0 + r1) * DMODEL + kb + 8];
    }

    const uint32_t sK = (uint32_t)__cvta_generic_to_shared(&Ks[0][0][0]);
    const uint32_t sV = (uint32_t)__cvta_generic_to_shared(&Vs[0][0][0]);
    const uint32_t stageB = 64 * QLD * 2;   // bytes per K (or V) stage

    auto issue_kv = [&](int k0, int buf) {
#pragma unroll
        for (int p = 0; p < 4; p++) {
            int i = t + p * 128;
            int row = i >> 3, c = (i & 7) * 8;
            uint32_t off = (uint32_t)buf * stageB + (uint32_t)((row * QLD + c) * 2);
            cp_async16(sK + off, &Kp[(size_t)(k0 + row) * DMODEL + c]);
            cp_async16(sV + off, &Vp[(size_t)(k0 + row) * DMODEL + c]);
        }
    };

    float Oc[8][4];
#pragma unroll
    for (int nb = 0; nb < 8; nb++)
#pragma unroll
        for (int j = 0; j < 4; j++) Oc[nb][j] = 0.0f;
    float m0 = -INFINITY, m1 = -INFINITY, l0 = 0.0f, l1 = 0.0f;

    issue_kv(0, 0);
    CP_COMMIT();

    int buf = 0;
    for (int kt = 0; kt <= qt; kt++) {
        __syncthreads();                 // prior-iter smem reads complete
        if (kt < qt) {
            issue_kv((kt + 1) * 64, buf ^ 1);
            CP_COMMIT();
            CP_WAIT(1);                  // tile kt arrived
        } else {
            CP_WAIT(0);
        }
        __syncthreads();                 // tile kt visible

        // ---- S = Q*K^T : 4 k16-steps x 8 n-blocks ----
        float Sc[8][4];
#pragma unroll
        for (int nb = 0; nb < 8; nb++)
#pragma unroll
            for (int j = 0; j < 4; j++) Sc[nb][j] = 0.0f;

#pragma unroll
        for (int ks = 0; ks < 4; ks++) {
            const int kb = ks * 16 + 2 * tc;
#pragma unroll
            for (int nb = 0; nb < 8; nb++) {
                uint32_t b0 = *(const uint32_t*)&Ks[buf][nb * 8 + g][kb];
                uint32_t b1 = *(const uint32_t*)&Ks[buf][nb * 8 + g][kb + 8];
                mma_f16_16x8x16(Sc[nb][0], Sc[nb][1], Sc[nb][2], Sc[nb][3],
                                qa[ks][0], qa[ks][1], qa[ks][2], qa[ks][3], b0, b1);
            }
        }

        // ---- causal mask (diagonal tile only) ----
        if (kt == qt) {
#pragma unroll
            for (int nb = 0; nb < 8; nb++) {
                int c0 = nb * 8 + tc * 2, c1 = c0 + 1;
                if (c0 > r0) Sc[nb][0] = -INFINITY;
                if (c1 > r0) Sc[nb][1] = -INFINITY;
                if (c0 > r1) Sc[nb][2] = -INFINITY;
                if (c1 > r1) Sc[nb][3] = -INFINITY;
            }
        }

        // ---- online softmax in registers ----
        float mx0 = -INFINITY, mx1 = -INFINITY;
#pragma unroll
        for (int nb = 0; nb < 8; nb++) {
            mx0 = fmaxf(mx0, fmaxf(Sc[nb][0], Sc[nb][1]));
            mx1 = fmaxf(mx1, fmaxf(Sc[nb][2], Sc[nb][3]));
        }
        mx0 = fmaxf(mx0, __shfl_xor_sync(0xffffffffu, mx0, 1));
        mx0 = fmaxf(mx0, __shfl_xor_sync(0xffffffffu, mx0, 2));
        mx1 = fmaxf(mx1, __shfl_xor_sync(0xffffffffu, mx1, 1));
        mx1 = fmaxf(mx1, __shfl_xor_sync(0xffffffffu, mx1, 2));
        const float mn0 = fmaxf(m0, mx0);
        const float mn1 = fmaxf(m1, mx1);
        float sum0 = 0.0f, sum1 = 0.0f;
#pragma unroll
        for (int nb = 0; nb < 8; nb++) {
            Sc[nb][0] = __expf(Sc[nb][0] - mn0);
            Sc[nb][1] = __expf(Sc[nb][1] - mn0);
            Sc[nb][2] = __expf(Sc[nb][2] - mn1);
            Sc[nb][3] = __expf(Sc[nb][3] - mn1);
            sum0 += Sc[nb][0] + Sc[nb][1];
            sum1 += Sc[nb][2] + Sc[nb][3];
        }
        sum0 += __shfl_xor_sync(0xffffffffu, sum0, 1);
        sum0 += __shfl_xor_sync(0xffffffffu, sum0, 2);
        sum1 += __shfl_xor_sync(0xffffffffu, sum1, 1);
        sum1 += __shfl_xor_sync(0xffffffffu, sum1, 2);
        const float a0s = __expf(m0 - mn0);
        const float a1s = __expf(m1 - mn1);
        l0 = l0 * a0s + sum0;  m0 = mn0;
        l1 = l1 * a1s + sum1;  m1 = mn1;
#pragma unroll
        for (int nb = 0; nb < 8; nb++) {
            Oc[nb][0] *= a0s; Oc[nb][1] *= a0s;
            Oc[nb][2] *= a1s; Oc[nb][3] *= a1s;
        }

        // ---- PV: P (regs -> f16) x V (smem via ldmatrix.trans) ----
        const uint32_t vlane = sV + (uint32_t)buf * stageB +
                               (uint32_t)((lane & 15) * QLD) * 2u;
#pragma unroll
        for (int tb = 0; tb < 4; tb++) {
            uint32_t pa0 = pack_h2(Sc[2 * tb][0],     Sc[2 * tb][1]);
            uint32_t pa1 = pack_h2(Sc[2 * tb][2],     Sc[2 * tb][3]);
            uint32_t pa2 = pack_h2(Sc[2 * tb + 1][0], Sc[2 * tb + 1][1]);
            uint32_t pa3 = pack_h2(Sc[2 * tb + 1][2], Sc[2 * tb + 1][3]);
            const uint32_t vrow = vlane + (uint32_t)(tb * 16 * QLD) * 2u;
#pragma unroll
            for (int nb = 0; nb < 8; nb++) {
                uint32_t b0, b1;
                ldmat_x2_trans(b0, b1, vrow + (uint32_t)(nb * 8) * 2u);
                mma_f16_16x8x16(Oc[nb][0], Oc[nb][1], Oc[nb][2], Oc[nb][3],
                                pa0, pa1, pa2, pa3, b0, b1);
            }
        }
        buf ^= 1;
    }

    // ---- epilogue: normalize, write context as f16 ----
    const float inv0 = 1.0f / l0;
    const float inv1 = 1.0f / l1;
#pragma unroll
    for (int nb = 0; nb < 8; nb++) {
        *(__half2*)&Cp[(size_t)(q0 + r0) * DMODEL + nb * 8 + tc * 2] =
            __floats2half2_rn(Oc[nb][0] * inv0, Oc[nb][1] * inv0);
        *(__half2*)&Cp[(size_t)(q0 + r1) * DMODEL + nb * 8 + tc * 2] =
            __floats2half2_rn(Oc[nb][2] * inv1, Oc[nb][3] * inv1);
    }
}

// ---------------- launcher ----------------
extern "C" void kernel_launch(void* const* d_in, const int* in_sizes, int n_in,
                              void* d_out, int out_size) {
    const float* input_Q = (const float*)d_in[0];
    const float* input_K = (const float*)d_in[1];
    const float* input_V = (const float*)d_in[2];
    // d_in[3] = attn_mask (causal, analytic), d_in[4] = flag
    const float* W_Q = (const float*)d_in[5];
    const float* W_K = (const float*)d_in[6];
    const float* W_V = (const float*)d_in[7];
    const float* W_O = (const float*)d_in[8];
    float* out = (float*)d_out;

    __half *inq, *ink, *inv, *wq, *wk, *wv, *wo, *qh, *kh, *vh, *ch;
    cudaGetSymbolAddress((void**)&inq, g_inQ);
    cudaGetSymbolAddress((void**)&ink, g_inK);
    cudaGetSymbolAddress((void**)&inv, g_inV);
    cudaGetSymbolAddress((void**)&wq, g_WQ);
    cudaGetSymbolAddress((void**)&wk, g_WK);
    cudaGetSymbolAddress((void**)&wv, g_WV);
    cudaGetSymbolAddress((void**)&wo, g_WO);
    cudaGetSymbolAddress((void**)&qh, g_Qh);
    cudaGetSymbolAddress((void**)&kh, g_Kh);
    cudaGetSymbolAddress((void**)&vh, g_Vh);
    cudaGetSymbolAddress((void**)&ch, g_Ctxh);

    // 1) convert inputs + weights to f16 (W_Q folded with 1/sqrt(d_k))
    dim3 cgrid_in(NTOK * DMODEL / 4 / 256, 1, 3);
    cvt_in<<<cgrid_in, 256>>>(input_Q, input_K, input_V, inq, ink, inv);
    dim3 cgrid_w(DMODEL * DMODEL / 4 / 256, 1, 4);
    cvt_w<<<cgrid_w, 256>>>(W_Q, W_K, W_V, W_O, wq, wk, wv, wo);

    // 2) fused QKV projections (f16 in, f16 out)
    dim3 ggrid(DMODEL / 128, NTOK / 128, 3);
    gemm_h<__half><<<ggrid, 256>>>(inq, ink, inv, wq, wk, wv, qh, kh, vh);

    // 3) attention (all f16, cp.async pipelined)
    dim3 agrid(SEQ / 64, NH, BATCH);
    attn_kernel<<<agrid, 128>>>();

    // 4) output projection (f16 in, f32 out)
    dim3 ogrid(DMODEL / 128, NTOK / 128, 1);
    gemm_h<float><<<ogrid, 256>>>(ch, ch, ch, wo, wo, wo, out, out, out);
}